// round 1
// baseline (speedup 1.0000x reference)
#include <cuda_runtime.h>

// Problem dims
#define ROWS   32768          // T*B = 4096*8
#define I_DIM  256
#define H_DIM  512
#define C_DIM  1024
#define O_DIM  512
#define NTILE2 (C_DIM / 128)  // 8 column tiles in GEMM2

// Scratch (device globals: no allocation allowed)
__device__ float g_h[ROWS * H_DIM];        // hidden activations [32768, 512]
__device__ float g_pmax[ROWS * NTILE2];    // per-(row, ntile) partial max
__device__ int   g_pidx[ROWS * NTILE2];    // per-(row, ntile) partial argmax
__device__ int   g_widx[ROWS];             // winner index per row
__device__ float g_table[C_DIM * O_DIM];   // log_softmax(h2o_w[:,c] + b) per concept

// ---------------------------------------------------------------------------
// Tiled SGEMM: C[M,N] = relu(A[M,K] * B[N,K]^T + bias[N])
// 128x128 block tile, BK=16, 256 threads, 8x8 register tile per thread.
// ARGMAX=false: A = Aext (x), writes g_h.
// ARGMAX=true : A = g_h,  computes per-row argmax of the 128-col tile and
//               writes (max, idx) partials instead of materializing C.
// ---------------------------------------------------------------------------
template<int K, int N, bool ARGMAX>
__global__ void __launch_bounds__(256, 2)
gemm_relu(const float* __restrict__ Aext,
          const float* __restrict__ B,
          const float* __restrict__ bias)
{
    __shared__ float As[16][128];
    __shared__ float Bs[16][128];

    const int t  = threadIdx.x;
    const int tx = t & 15;        // 0..15 -> column group
    const int ty = t >> 4;        // 0..15 -> row group
    const int bm = blockIdx.y * 128;
    const int bn = blockIdx.x * 128;

    const float* A = ARGMAX ? (const float*)g_h : Aext;

    float acc[8][8];
#pragma unroll
    for (int i = 0; i < 8; i++)
#pragma unroll
        for (int j = 0; j < 8; j++) acc[i][j] = 0.0f;

    const float* Ab = A + (size_t)bm * K;
    const float* Bb = B + (size_t)bn * K;

    for (int k0 = 0; k0 < K; k0 += 16) {
        // Load 128x16 A tile and 128x16 B tile, transposed into smem.
        // 512 float4 per tile, 2 per thread, coalesced (idx = i*256 + t).
#pragma unroll
        for (int i = 0; i < 2; i++) {
            int idx = i * 256 + t;       // 0..511
            int row = idx >> 2;          // 0..127
            int kq  = (idx & 3) << 2;    // 0,4,8,12
            float4 av = *(const float4*)(Ab + (size_t)row * K + k0 + kq);
            As[kq + 0][row] = av.x;
            As[kq + 1][row] = av.y;
            As[kq + 2][row] = av.z;
            As[kq + 3][row] = av.w;
            float4 bv = *(const float4*)(Bb + (size_t)row * K + k0 + kq);
            Bs[kq + 0][row] = bv.x;
            Bs[kq + 1][row] = bv.y;
            Bs[kq + 2][row] = bv.z;
            Bs[kq + 3][row] = bv.w;
        }
        __syncthreads();

#pragma unroll
        for (int kk = 0; kk < 16; kk++) {
            float a[8], b[8];
            *(float4*)&a[0] = *(const float4*)&As[kk][ty * 8];
            *(float4*)&a[4] = *(const float4*)&As[kk][ty * 8 + 4];
            *(float4*)&b[0] = *(const float4*)&Bs[kk][tx * 8];
            *(float4*)&b[4] = *(const float4*)&Bs[kk][tx * 8 + 4];
#pragma unroll
            for (int i = 0; i < 8; i++)
#pragma unroll
                for (int j = 0; j < 8; j++)
                    acc[i][j] = fmaf(a[i], b[j], acc[i][j]);
        }
        __syncthreads();
    }

    float bv[8];
#pragma unroll
    for (int j = 0; j < 8; j++) bv[j] = bias[bn + tx * 8 + j];

    if (!ARGMAX) {
        // Epilogue: relu + store to g_h
#pragma unroll
        for (int i = 0; i < 8; i++) {
            int row = bm + ty * 8 + i;
            float4 o0, o1;
            o0.x = fmaxf(acc[i][0] + bv[0], 0.0f);
            o0.y = fmaxf(acc[i][1] + bv[1], 0.0f);
            o0.z = fmaxf(acc[i][2] + bv[2], 0.0f);
            o0.w = fmaxf(acc[i][3] + bv[3], 0.0f);
            o1.x = fmaxf(acc[i][4] + bv[4], 0.0f);
            o1.y = fmaxf(acc[i][5] + bv[5], 0.0f);
            o1.z = fmaxf(acc[i][6] + bv[6], 0.0f);
            o1.w = fmaxf(acc[i][7] + bv[7], 0.0f);
            float* dst = g_h + (size_t)row * N + bn + tx * 8;
            *(float4*)dst       = o0;
            *(float4*)(dst + 4) = o1;
        }
    } else {
        // Epilogue: relu + per-row argmax over this 128-col tile.
        // Thread covers 8 cols; half-warp (16 lanes sharing ty) covers 128.
#pragma unroll
        for (int i = 0; i < 8; i++) {
            float m  = fmaxf(acc[i][0] + bv[0], 0.0f);
            int   mi = bn + tx * 8;
#pragma unroll
            for (int j = 1; j < 8; j++) {
                float v = fmaxf(acc[i][j] + bv[j], 0.0f);
                if (v > m) { m = v; mi = bn + tx * 8 + j; }
            }
            // reduce across the 16 lanes sharing this row (lanes 0-15 / 16-31)
#pragma unroll
            for (int off = 8; off > 0; off >>= 1) {
                float om = __shfl_down_sync(0xffffffffu, m, off);
                int   oi = __shfl_down_sync(0xffffffffu, mi, off);
                if (om > m || (om == m && oi < mi)) { m = om; mi = oi; }
            }
            if (tx == 0) {
                int row = bm + ty * 8 + i;
                g_pmax[row * NTILE2 + blockIdx.x] = m;
                g_pidx[row * NTILE2 + blockIdx.x] = mi;
            }
        }
    }
}

// Reduce 8 partial (max, idx) per row to the winner (lowest index wins ties).
__global__ void wta_reduce()
{
    int row = blockIdx.x * 256 + threadIdx.x;
    float m  = g_pmax[row * NTILE2];
    int   mi = g_pidx[row * NTILE2];
#pragma unroll
    for (int n = 1; n < NTILE2; n++) {
        float v = g_pmax[row * NTILE2 + n];
        if (v > m) { m = v; mi = g_pidx[row * NTILE2 + n]; }  // tiles ascend in col
    }
    g_widx[row] = mi;
}

// table[c, o] = log_softmax_o(h2o_w[o, c] + h2o_b[o]); one block per concept c.
__global__ void build_table(const float* __restrict__ w, const float* __restrict__ b)
{
    __shared__ float red[O_DIM];
    int c = blockIdx.x;
    int o = threadIdx.x;
    float v = w[(size_t)o * C_DIM + c] + b[o];

    red[o] = v;
    __syncthreads();
#pragma unroll
    for (int s = O_DIM / 2; s > 0; s >>= 1) {
        if (o < s) red[o] = fmaxf(red[o], red[o + s]);
        __syncthreads();
    }
    float mx = red[0];
    __syncthreads();

    float e = __expf(v - mx) * 0.0f + expf(v - mx);  // use precise expf
    red[o] = e;
    __syncthreads();
#pragma unroll
    for (int s = O_DIM / 2; s > 0; s >>= 1) {
        if (o < s) red[o] += red[o + s];
        __syncthreads();
    }
    float lse = logf(red[0]) + mx;
    g_table[(size_t)c * O_DIM + o] = v - lse;
}

// out[row, :] = table[widx[row], :]   (512 floats = 128 float4 per row)
__global__ void gather_out(float* __restrict__ out)
{
    int row = blockIdx.x;
    int c = g_widx[row];
    const float4* src = (const float4*)(g_table + (size_t)c * O_DIM);
    float4* dst = (float4*)(out + (size_t)row * O_DIM);
    dst[threadIdx.x] = src[threadIdx.x];
}

extern "C" void kernel_launch(void* const* d_in, const int* in_sizes, int n_in,
                              void* d_out, int out_size)
{
    const float* x     = (const float*)d_in[0];
    // d_in[1] = hidden1 (unused dummy)
    const float* i2m_w = (const float*)d_in[2];
    const float* i2m_b = (const float*)d_in[3];
    const float* m2h_w = (const float*)d_in[4];
    const float* m2h_b = (const float*)d_in[5];
    const float* h2o_w = (const float*)d_in[6];
    const float* h2o_b = (const float*)d_in[7];
    float* out = (float*)d_out;

    // 1) h = relu(x @ i2m_w^T + b)           [32768, 512]
    gemm_relu<I_DIM, H_DIM, false>
        <<<dim3(H_DIM / 128, ROWS / 128), 256>>>(x, i2m_w, i2m_b);

    // 2) fused c = relu(h @ m2h_w^T + b) + per-tile argmax (c never stored)
    gemm_relu<H_DIM, C_DIM, true>
        <<<dim3(C_DIM / 128, ROWS / 128), 256>>>(nullptr, m2h_w, m2h_b);

    // 3) winner per row
    wta_reduce<<<ROWS / 256, 256>>>();

    // 4) log_softmax table over all 1024 possible winner columns
    build_table<<<C_DIM, O_DIM>>>(h2o_w, h2o_b);

    // 5) gather output rows
    gather_out<<<ROWS, O_DIM / 4>>>(out);
}

// round 3
// speedup vs baseline: 2.4898x; 2.4898x over previous
#include <cuda_runtime.h>
#include <cuda_bf16.h>
#include <stdint.h>

// Problem dims
#define ROWS   32768          // T*B
#define I_DIM  256
#define H_DIM  512
#define C_DIM  1024
#define O_DIM  512

// Scratch (device globals: no allocation allowed)
__device__ float         g_h[(size_t)ROWS * H_DIM];     // fp32 hidden
__device__ __nv_bfloat16 g_hb[(size_t)ROWS * H_DIM];    // bf16 hidden
__device__ __nv_bfloat16 g_w2b[(size_t)C_DIM * H_DIM];  // bf16 m2h_w
__device__ float         g_c[(size_t)ROWS * C_DIM];     // approx concept pre-acts
__device__ int           g_widx[ROWS];                  // winner index per row
__device__ float         g_table[(size_t)C_DIM * O_DIM];// log_softmax table

// ---------------------------------------------------------------------------
// PTX helpers (base sm_103 ISA only: cp.async / ldmatrix / mma.sync)
// ---------------------------------------------------------------------------
__device__ __forceinline__ uint32_t smem_u32(const void* p) {
    uint32_t a;
    asm("{ .reg .u64 t; cvta.to.shared.u64 t, %1; cvt.u32.u64 %0, t; }" : "=r"(a) : "l"(p));
    return a;
}
#define CP_ASYNC16(dst, src) \
    asm volatile("cp.async.cg.shared.global [%0], [%1], 16;" :: "r"(dst), "l"(src) : "memory")
#define CP_COMMIT()  asm volatile("cp.async.commit_group;" ::: "memory")
#define CP_WAIT(n)   asm volatile("cp.async.wait_group %0;" :: "n"(n) : "memory")

__device__ __forceinline__ void ldsm_x4(uint32_t& r0, uint32_t& r1, uint32_t& r2, uint32_t& r3,
                                        uint32_t addr) {
    asm volatile("ldmatrix.sync.aligned.m8n8.x4.shared.b16 {%0,%1,%2,%3}, [%4];"
                 : "=r"(r0), "=r"(r1), "=r"(r2), "=r"(r3) : "r"(addr));
}
__device__ __forceinline__ void mma_bf16(float* d, const uint32_t* a, const uint32_t* b) {
    asm volatile("mma.sync.aligned.m16n8k16.row.col.f32.bf16.bf16.f32 "
                 "{%0,%1,%2,%3}, {%4,%5,%6,%7}, {%8,%9}, {%0,%1,%2,%3};"
                 : "+f"(d[0]), "+f"(d[1]), "+f"(d[2]), "+f"(d[3])
                 : "r"(a[0]), "r"(a[1]), "r"(a[2]), "r"(a[3]), "r"(b[0]), "r"(b[1]));
}

// ---------------------------------------------------------------------------
// GEMM1 (fp32 SIMT): g_h = relu(x @ i2m_w^T + b); also emits bf16 copy g_hb.
// ---------------------------------------------------------------------------
__global__ void __launch_bounds__(256, 2)
gemm1(const float* __restrict__ A, const float* __restrict__ B,
      const float* __restrict__ bias)
{
    const int K = I_DIM, N = H_DIM;
    __shared__ float As[16][128];
    __shared__ float Bs[16][128];

    const int t  = threadIdx.x;
    const int tx = t & 15, ty = t >> 4;
    const int bm = blockIdx.y * 128, bn = blockIdx.x * 128;

    float acc[8][8];
#pragma unroll
    for (int i = 0; i < 8; i++)
#pragma unroll
        for (int j = 0; j < 8; j++) acc[i][j] = 0.0f;

    const float* Ab = A + (size_t)bm * K;
    const float* Bb = B + (size_t)bn * K;

    for (int k0 = 0; k0 < K; k0 += 16) {
#pragma unroll
        for (int i = 0; i < 2; i++) {
            int idx = i * 256 + t;
            int row = idx >> 2;
            int kq  = (idx & 3) << 2;
            float4 av = *(const float4*)(Ab + (size_t)row * K + k0 + kq);
            As[kq+0][row] = av.x; As[kq+1][row] = av.y;
            As[kq+2][row] = av.z; As[kq+3][row] = av.w;
            float4 bv = *(const float4*)(Bb + (size_t)row * K + k0 + kq);
            Bs[kq+0][row] = bv.x; Bs[kq+1][row] = bv.y;
            Bs[kq+2][row] = bv.z; Bs[kq+3][row] = bv.w;
        }
        __syncthreads();
#pragma unroll
        for (int kk = 0; kk < 16; kk++) {
            float a[8], b[8];
            *(float4*)&a[0] = *(const float4*)&As[kk][ty*8];
            *(float4*)&a[4] = *(const float4*)&As[kk][ty*8+4];
            *(float4*)&b[0] = *(const float4*)&Bs[kk][tx*8];
            *(float4*)&b[4] = *(const float4*)&Bs[kk][tx*8+4];
#pragma unroll
            for (int i = 0; i < 8; i++)
#pragma unroll
                for (int j = 0; j < 8; j++)
                    acc[i][j] = fmaf(a[i], b[j], acc[i][j]);
        }
        __syncthreads();
    }

    float bv[8];
#pragma unroll
    for (int j = 0; j < 8; j++) bv[j] = bias[bn + tx*8 + j];

#pragma unroll
    for (int i = 0; i < 8; i++) {
        int row = bm + ty*8 + i;
        float v[8];
#pragma unroll
        for (int j = 0; j < 8; j++) v[j] = fmaxf(acc[i][j] + bv[j], 0.0f);
        float* dst = g_h + (size_t)row * N + bn + tx*8;
        *(float4*)dst     = make_float4(v[0], v[1], v[2], v[3]);
        *(float4*)(dst+4) = make_float4(v[4], v[5], v[6], v[7]);
        __nv_bfloat16 hb[8];
#pragma unroll
        for (int j = 0; j < 8; j++) hb[j] = __float2bfloat16(v[j]);
        *(uint4*)(g_hb + (size_t)row * N + bn + tx*8) = *(uint4*)hb;
    }
}

// convert m2h_w (fp32 [C,H]) -> bf16
__global__ void conv_w2(const float* __restrict__ w)
{
    int i = blockIdx.x * 256 + threadIdx.x;   // over C*H/4 float4s
    float4 v = *(const float4*)(w + (size_t)i * 4);
    __nv_bfloat16 b[4] = { __float2bfloat16(v.x), __float2bfloat16(v.y),
                           __float2bfloat16(v.z), __float2bfloat16(v.w) };
    *(uint2*)(g_w2b + (size_t)i * 4) = *(uint2*)b;
}

// ---------------------------------------------------------------------------
// GEMM2 via mma.sync (HMMA bf16, fp32 accum): g_c = g_hb @ g_w2b^T + bias
// Block 128x128, 8 warps (2x4), warp tile 64x32. BK=32, 2-stage cp.async.
// Smem rows padded to 40 elems (80B) -> LDSM bank stride 20 mod 32 (no conflicts).
// ---------------------------------------------------------------------------
#define BK        32
#define SROW      40                      // padded row length (bf16 elems)
#define STAGE_B   (128 * SROW * 2)        // bytes per stage buffer (10240)

__global__ void __launch_bounds__(256)
gemm2_mma(const float* __restrict__ bias)
{
    __shared__ __align__(16) __nv_bfloat16 As[2][128 * SROW];
    __shared__ __align__(16) __nv_bfloat16 Bs[2][128 * SROW];

    const int t   = threadIdx.x;
    const int wid = t >> 5, lid = t & 31;
    const int wm  = wid & 1;              // 2 warp rows (64 each)
    const int wn  = wid >> 1;             // 4 warp cols (32 each)
    const int bm  = blockIdx.y * 128, bn = blockIdx.x * 128;

    const uint32_t sA = smem_u32(As);
    const uint32_t sB = smem_u32(Bs);

    // per-thread cp.async piece: p = t + i*256 ; row = p>>2, seg = p&3
    const int r0l = t >> 2,        s0 = (t & 3);
    const int r1l = (t + 256) >> 2, s1 = (t & 3);

    float d[4][4][4];
#pragma unroll
    for (int mi = 0; mi < 4; mi++)
#pragma unroll
        for (int ni = 0; ni < 4; ni++)
#pragma unroll
            for (int r = 0; r < 4; r++) d[mi][ni][r] = 0.0f;

    // prefetch stage 0
    {
        const int k0 = 0;
        CP_ASYNC16(sA + r0l*80 + s0*16, g_hb  + (size_t)(bm + r0l)*H_DIM + k0 + s0*8);
        CP_ASYNC16(sB + r0l*80 + s0*16, g_w2b + (size_t)(bn + r0l)*H_DIM + k0 + s0*8);
        CP_ASYNC16(sA + r1l*80 + s1*16, g_hb  + (size_t)(bm + r1l)*H_DIM + k0 + s1*8);
        CP_ASYNC16(sB + r1l*80 + s1*16, g_w2b + (size_t)(bn + r1l)*H_DIM + k0 + s1*8);
        CP_COMMIT();
    }

    // ldmatrix lane addressing (constant across k-loop except ks/buf offset)
    const int rowA = wm*64 + (lid & 15);
    const int colAofs = (lid < 16) ? 0 : 8;
    const int rowB = wn*32 + ((lid >> 4) & 1)*8 + (lid & 7);
    const int colBofs = ((lid >> 3) & 1)*8;

    const int NIT = H_DIM / BK;           // 16
    for (int kt = 0; kt < NIT; kt++) {
        const int buf = kt & 1;
        if (kt + 1 < NIT) {
            const int k0 = (kt + 1) * BK;
            const uint32_t dA = sA + (1 - buf) * STAGE_B;
            const uint32_t dB = sB + (1 - buf) * STAGE_B;
            CP_ASYNC16(dA + r0l*80 + s0*16, g_hb  + (size_t)(bm + r0l)*H_DIM + k0 + s0*8);
            CP_ASYNC16(dB + r0l*80 + s0*16, g_w2b + (size_t)(bn + r0l)*H_DIM + k0 + s0*8);
            CP_ASYNC16(dA + r1l*80 + s1*16, g_hb  + (size_t)(bm + r1l)*H_DIM + k0 + s1*8);
            CP_ASYNC16(dB + r1l*80 + s1*16, g_w2b + (size_t)(bn + r1l)*H_DIM + k0 + s1*8);
            CP_COMMIT();
            CP_WAIT(1);
        } else {
            CP_WAIT(0);
        }
        __syncthreads();

        const uint32_t aB = sA + buf * STAGE_B;
        const uint32_t bB = sB + buf * STAGE_B;
#pragma unroll
        for (int ks = 0; ks < BK; ks += 16) {
            uint32_t a[4][4];
#pragma unroll
            for (int mi = 0; mi < 4; mi++)
                ldsm_x4(a[mi][0], a[mi][1], a[mi][2], a[mi][3],
                        aB + (uint32_t)(rowA + mi*16) * 80 + (uint32_t)(ks + colAofs) * 2);
            uint32_t b[4][2];
#pragma unroll
            for (int np = 0; np < 2; np++) {
                uint32_t q0, q1, q2, q3;
                ldsm_x4(q0, q1, q2, q3,
                        bB + (uint32_t)(rowB + np*16) * 80 + (uint32_t)(ks + colBofs) * 2);
                b[np*2][0] = q0; b[np*2][1] = q1;
                b[np*2+1][0] = q2; b[np*2+1][1] = q3;
            }
#pragma unroll
            for (int mi = 0; mi < 4; mi++)
#pragma unroll
                for (int ni = 0; ni < 4; ni++)
                    mma_bf16(d[mi][ni], a[mi], b[ni]);
        }
        __syncthreads();
    }

    // epilogue: + bias -> g_c
    const int cbase = bn + wn*32 + (lid & 3) * 2;
#pragma unroll
    for (int ni = 0; ni < 4; ni++) {
        const int col = cbase + ni*8;
        const float b0 = __ldg(bias + col), b1 = __ldg(bias + col + 1);
#pragma unroll
        for (int mi = 0; mi < 4; mi++) {
            const int r0 = bm + wm*64 + mi*16 + (lid >> 2);
            float2 v0 = make_float2(d[mi][ni][0] + b0, d[mi][ni][1] + b1);
            float2 v1 = make_float2(d[mi][ni][2] + b0, d[mi][ni][3] + b1);
            *(float2*)(g_c + (size_t)r0 * C_DIM + col)       = v0;
            *(float2*)(g_c + (size_t)(r0 + 8) * C_DIM + col) = v1;
        }
    }
}

// ---------------------------------------------------------------------------
// Scan + exact refinement: winner per row from approx g_c, verified in fp32.
// One warp per row; candidates = all j with c~_j >= max - margin.
// ---------------------------------------------------------------------------
__global__ void __launch_bounds__(256)
scan_refine(const float* __restrict__ w, const float* __restrict__ b)
{
    __shared__ int cnt[8];
    __shared__ int cand[8][64];
    const int wid = threadIdx.x >> 5, lid = threadIdx.x & 31;
    const int row = blockIdx.x * 8 + wid;

    const float* crow = g_c + (size_t)row * C_DIM;
    float mx = -1e30f;
#pragma unroll
    for (int it = 0; it < 32; it++) mx = fmaxf(mx, crow[lid + it * 32]);
#pragma unroll
    for (int off = 16; off > 0; off >>= 1)
        mx = fmaxf(mx, __shfl_xor_sync(0xffffffffu, mx, off));

    float margin = 0.06f * fabsf(mx) + 1e-5f;
    if (lid == 0) cnt[wid] = 0;
    __syncwarp();
#pragma unroll
    for (int it = 0; it < 32; it++) {
        int j = lid + it * 32;
        if (crow[j] >= mx - margin) {
            int p = atomicAdd(&cnt[wid], 1);
            if (p < 64) cand[wid][p] = j;
        }
    }
    __syncwarp();
    int n = min(cnt[wid], 64);

    const float* hrow = g_h + (size_t)row * H_DIM;
    float best = -1e30f; int bidx = C_DIM;
    for (int ci = 0; ci < n; ci++) {
        int j = cand[wid][ci];
        const float* wr = w + (size_t)j * H_DIM;
        float s = 0.0f;
#pragma unroll
        for (int i = 0; i < 16; i++) {
            int k = lid + i * 32;
            s = fmaf(hrow[k], wr[k], s);
        }
#pragma unroll
        for (int off = 16; off > 0; off >>= 1)
            s += __shfl_xor_sync(0xffffffffu, s, off);
        s += b[j];
        if (s > best || (s == best && j < bidx)) { best = s; bidx = j; }
    }
    if (lid == 0) g_widx[row] = bidx;
}

// table[c, o] = log_softmax_o(h2o_w[o, c] + h2o_b[o])
__global__ void build_table(const float* __restrict__ w, const float* __restrict__ b)
{
    __shared__ float red[O_DIM];
    int c = blockIdx.x, o = threadIdx.x;
    float v = w[(size_t)o * C_DIM + c] + b[o];
    red[o] = v;
    __syncthreads();
#pragma unroll
    for (int s = O_DIM / 2; s > 0; s >>= 1) {
        if (o < s) red[o] = fmaxf(red[o], red[o + s]);
        __syncthreads();
    }
    float mx = red[0];
    __syncthreads();
    red[o] = expf(v - mx);
    __syncthreads();
#pragma unroll
    for (int s = O_DIM / 2; s > 0; s >>= 1) {
        if (o < s) red[o] += red[o + s];
        __syncthreads();
    }
    float lse = logf(red[0]) + mx;
    g_table[(size_t)c * O_DIM + o] = v - lse;
}

__global__ void gather_out(float* __restrict__ out)
{
    int row = blockIdx.x;
    int c = g_widx[row];
    const float4* src = (const float4*)(g_table + (size_t)c * O_DIM);
    float4* dst = (float4*)(out + (size_t)row * O_DIM);
    dst[threadIdx.x] = src[threadIdx.x];
}

extern "C" void kernel_launch(void* const* d_in, const int* in_sizes, int n_in,
                              void* d_out, int out_size)
{
    const float* x     = (const float*)d_in[0];
    const float* i2m_w = (const float*)d_in[2];
    const float* i2m_b = (const float*)d_in[3];
    const float* m2h_w = (const float*)d_in[4];
    const float* m2h_b = (const float*)d_in[5];
    const float* h2o_w = (const float*)d_in[6];
    const float* h2o_b = (const float*)d_in[7];
    float* out = (float*)d_out;

    // 1) h = relu(x @ i2m_w^T + b)  (fp32 + bf16 copy)
    gemm1<<<dim3(H_DIM/128, ROWS/128), 256>>>(x, i2m_w, i2m_b);

    // weight conversion (independent of gemm1)
    conv_w2<<<(C_DIM*H_DIM/4)/256, 256>>>(m2h_w);

    // 2) approx c = h_bf16 @ w_bf16^T + b  via HMMA mma.sync
    gemm2_mma<<<dim3(C_DIM/128, ROWS/128), 256>>>(m2h_b);

    // 3) winner per row, fp32-verified
    scan_refine<<<ROWS/8, 256>>>(m2h_w, m2h_b);

    // 4) log_softmax table + 5) gather
    build_table<<<C_DIM, O_DIM>>>(h2o_w, h2o_b);
    gather_out<<<ROWS, O_DIM/4>>>(out);
}

// round 4
// speedup vs baseline: 2.5661x; 1.0306x over previous
#include <cuda_runtime.h>
#include <cuda_bf16.h>
#include <stdint.h>

// Problem dims
#define ROWS   32768          // T*B
#define I_DIM  256
#define H_DIM  512
#define C_DIM  1024
#define O_DIM  512

// Scratch (device globals: no allocation allowed)
__device__ float         g_h[(size_t)ROWS * H_DIM];     // fp32 hidden (exact)
__device__ __nv_bfloat16 g_hb[(size_t)ROWS * H_DIM];    // bf16 hidden
__device__ __nv_bfloat16 g_w2b[(size_t)C_DIM * H_DIM];  // bf16 m2h_w
__device__ __nv_bfloat16 g_cb[(size_t)ROWS * C_DIM];    // approx concept pre-acts (bf16)
__device__ int           g_widx[ROWS];                  // winner index per row
__device__ float         g_table[(size_t)C_DIM * O_DIM];// log_softmax table

// ---------------------------------------------------------------------------
// PTX helpers (base sm_103 ISA: cp.async / ldmatrix / mma.sync / f32x2)
// ---------------------------------------------------------------------------
__device__ __forceinline__ uint32_t smem_u32(const void* p) {
    uint32_t a;
    asm("{ .reg .u64 t; cvta.to.shared.u64 t, %1; cvt.u32.u64 %0, t; }" : "=r"(a) : "l"(p));
    return a;
}
#define CP_ASYNC16(dst, src) \
    asm volatile("cp.async.cg.shared.global [%0], [%1], 16;" :: "r"(dst), "l"(src) : "memory")
#define CP_COMMIT()  asm volatile("cp.async.commit_group;" ::: "memory")
#define CP_WAIT(n)   asm volatile("cp.async.wait_group %0;" :: "n"(n) : "memory")

__device__ __forceinline__ void ldsm_x4(uint32_t& r0, uint32_t& r1, uint32_t& r2, uint32_t& r3,
                                        uint32_t addr) {
    asm volatile("ldmatrix.sync.aligned.m8n8.x4.shared.b16 {%0,%1,%2,%3}, [%4];"
                 : "=r"(r0), "=r"(r1), "=r"(r2), "=r"(r3) : "r"(addr));
}
__device__ __forceinline__ void mma_bf16(float* d, const uint32_t* a, const uint32_t* b) {
    asm volatile("mma.sync.aligned.m16n8k16.row.col.f32.bf16.bf16.f32 "
                 "{%0,%1,%2,%3}, {%4,%5,%6,%7}, {%8,%9}, {%0,%1,%2,%3};"
                 : "+f"(d[0]), "+f"(d[1]), "+f"(d[2]), "+f"(d[3])
                 : "r"(a[0]), "r"(a[1]), "r"(a[2]), "r"(a[3]), "r"(b[0]), "r"(b[1]));
}

// ---------------------------------------------------------------------------
// GEMM1 (fp32, packed FFMA2): g_h = relu(x @ i2m_w^T + b); emits bf16 copy.
// 128x128 tile, BK=16, 256 threads, 8x8 register tile via fma.rn.f32x2.
// ---------------------------------------------------------------------------
__global__ void __launch_bounds__(256, 2)
gemm1(const float* __restrict__ A, const float* __restrict__ B,
      const float* __restrict__ bias)
{
    const int K = I_DIM, N = H_DIM;
    __shared__ float As[16][128];
    __shared__ float Bs[16][128];

    const int t  = threadIdx.x;
    const int tx = t & 15, ty = t >> 4;
    const int bm = blockIdx.y * 128, bn = blockIdx.x * 128;

    // packed accumulators: acc2[i][j] holds cols (2j, 2j+1) for row i
    unsigned long long acc2[8][4];
#pragma unroll
    for (int i = 0; i < 8; i++)
#pragma unroll
        for (int j = 0; j < 4; j++) acc2[i][j] = 0ULL;

    const float* Ab = A + (size_t)bm * K;
    const float* Bb = B + (size_t)bn * K;

    for (int k0 = 0; k0 < K; k0 += 16) {
#pragma unroll
        for (int i = 0; i < 2; i++) {
            int idx = i * 256 + t;
            int row = idx >> 2;
            int kq  = (idx & 3) << 2;
            float4 av = *(const float4*)(Ab + (size_t)row * K + k0 + kq);
            As[kq+0][row] = av.x; As[kq+1][row] = av.y;
            As[kq+2][row] = av.z; As[kq+3][row] = av.w;
            float4 bv = *(const float4*)(Bb + (size_t)row * K + k0 + kq);
            Bs[kq+0][row] = bv.x; Bs[kq+1][row] = bv.y;
            Bs[kq+2][row] = bv.z; Bs[kq+3][row] = bv.w;
        }
        __syncthreads();
#pragma unroll
        for (int kk = 0; kk < 16; kk++) {
            float a[8];
            *(float4*)&a[0] = *(const float4*)&As[kk][ty*8];
            *(float4*)&a[4] = *(const float4*)&As[kk][ty*8+4];
            ulonglong2 q0 = *(const ulonglong2*)&Bs[kk][tx*8];
            ulonglong2 q1 = *(const ulonglong2*)&Bs[kk][tx*8+4];
            unsigned long long bb[4] = { q0.x, q0.y, q1.x, q1.y };
#pragma unroll
            for (int i = 0; i < 8; i++) {
                unsigned long long aa;
                asm("mov.b64 %0, {%1, %1};" : "=l"(aa) : "f"(a[i]));
#pragma unroll
                for (int j = 0; j < 4; j++)
                    asm("fma.rn.f32x2 %0, %1, %2, %0;"
                        : "+l"(acc2[i][j]) : "l"(aa), "l"(bb[j]));
            }
        }
        __syncthreads();
    }

    float bv[8];
#pragma unroll
    for (int j = 0; j < 8; j++) bv[j] = bias[bn + tx*8 + j];

#pragma unroll
    for (int i = 0; i < 8; i++) {
        int row = bm + ty*8 + i;
        float v[8];
#pragma unroll
        for (int j = 0; j < 4; j++) {
            float lo, hi;
            asm("mov.b64 {%0, %1}, %2;" : "=f"(lo), "=f"(hi) : "l"(acc2[i][j]));
            v[2*j]   = fmaxf(lo + bv[2*j],   0.0f);
            v[2*j+1] = fmaxf(hi + bv[2*j+1], 0.0f);
        }
        float* dst = g_h + (size_t)row * N + bn + tx*8;
        *(float4*)dst     = make_float4(v[0], v[1], v[2], v[3]);
        *(float4*)(dst+4) = make_float4(v[4], v[5], v[6], v[7]);
        __nv_bfloat16 hb[8];
#pragma unroll
        for (int j = 0; j < 8; j++) hb[j] = __float2bfloat16(v[j]);
        *(uint4*)(g_hb + (size_t)row * N + bn + tx*8) = *(uint4*)hb;
    }
}

// convert m2h_w (fp32 [C,H]) -> bf16
__global__ void conv_w2(const float* __restrict__ w)
{
    int i = blockIdx.x * 256 + threadIdx.x;   // over C*H/4 float4s
    float4 v = *(const float4*)(w + (size_t)i * 4);
    __nv_bfloat16 b[4] = { __float2bfloat16(v.x), __float2bfloat16(v.y),
                           __float2bfloat16(v.z), __float2bfloat16(v.w) };
    *(uint2*)(g_w2b + (size_t)i * 4) = *(uint2*)b;
}

// ---------------------------------------------------------------------------
// GEMM2 via mma.sync (HMMA bf16, fp32 accum): g_cb = bf16(g_hb @ g_w2b^T + b)
// Block 128x128, 8 warps (2x4), warp tile 64x32. BK=32, 2-stage cp.async.
// ---------------------------------------------------------------------------
#define BK        32
#define SROW      40                      // padded row length (bf16 elems)
#define STAGE_B   (128 * SROW * 2)        // bytes per stage buffer (10240)

__global__ void __launch_bounds__(256)
gemm2_mma(const float* __restrict__ bias)
{
    __shared__ __align__(16) __nv_bfloat16 As[2][128 * SROW];
    __shared__ __align__(16) __nv_bfloat16 Bs[2][128 * SROW];

    const int t   = threadIdx.x;
    const int wid = t >> 5, lid = t & 31;
    const int wm  = wid & 1;              // 2 warp rows (64 each)
    const int wn  = wid >> 1;             // 4 warp cols (32 each)
    const int bm  = blockIdx.y * 128, bn = blockIdx.x * 128;

    const uint32_t sA = smem_u32(As);
    const uint32_t sB = smem_u32(Bs);

    const int r0l = t >> 2,         s0 = (t & 3);
    const int r1l = (t + 256) >> 2, s1 = (t & 3);

    float d[4][4][4];
#pragma unroll
    for (int mi = 0; mi < 4; mi++)
#pragma unroll
        for (int ni = 0; ni < 4; ni++)
#pragma unroll
            for (int r = 0; r < 4; r++) d[mi][ni][r] = 0.0f;

    // prefetch stage 0
    {
        CP_ASYNC16(sA + r0l*80 + s0*16, g_hb  + (size_t)(bm + r0l)*H_DIM + s0*8);
        CP_ASYNC16(sB + r0l*80 + s0*16, g_w2b + (size_t)(bn + r0l)*H_DIM + s0*8);
        CP_ASYNC16(sA + r1l*80 + s1*16, g_hb  + (size_t)(bm + r1l)*H_DIM + s1*8);
        CP_ASYNC16(sB + r1l*80 + s1*16, g_w2b + (size_t)(bn + r1l)*H_DIM + s1*8);
        CP_COMMIT();
    }

    const int rowA = wm*64 + (lid & 15);
    const int colAofs = (lid < 16) ? 0 : 8;
    const int rowB = wn*32 + ((lid >> 4) & 1)*8 + (lid & 7);
    const int colBofs = ((lid >> 3) & 1)*8;

    const int NIT = H_DIM / BK;           // 16
    for (int kt = 0; kt < NIT; kt++) {
        const int buf = kt & 1;
        if (kt + 1 < NIT) {
            const int k0 = (kt + 1) * BK;
            const uint32_t dA = sA + (1 - buf) * STAGE_B;
            const uint32_t dB = sB + (1 - buf) * STAGE_B;
            CP_ASYNC16(dA + r0l*80 + s0*16, g_hb  + (size_t)(bm + r0l)*H_DIM + k0 + s0*8);
            CP_ASYNC16(dB + r0l*80 + s0*16, g_w2b + (size_t)(bn + r0l)*H_DIM + k0 + s0*8);
            CP_ASYNC16(dA + r1l*80 + s1*16, g_hb  + (size_t)(bm + r1l)*H_DIM + k0 + s1*8);
            CP_ASYNC16(dB + r1l*80 + s1*16, g_w2b + (size_t)(bn + r1l)*H_DIM + k0 + s1*8);
            CP_COMMIT();
            CP_WAIT(1);
        } else {
            CP_WAIT(0);
        }
        __syncthreads();

        const uint32_t aB = sA + buf * STAGE_B;
        const uint32_t bB = sB + buf * STAGE_B;
#pragma unroll
        for (int ks = 0; ks < BK; ks += 16) {
            uint32_t a[4][4];
#pragma unroll
            for (int mi = 0; mi < 4; mi++)
                ldsm_x4(a[mi][0], a[mi][1], a[mi][2], a[mi][3],
                        aB + (uint32_t)(rowA + mi*16) * 80 + (uint32_t)(ks + colAofs) * 2);
            uint32_t b[4][2];
#pragma unroll
            for (int np = 0; np < 2; np++) {
                uint32_t q0, q1, q2, q3;
                ldsm_x4(q0, q1, q2, q3,
                        bB + (uint32_t)(rowB + np*16) * 80 + (uint32_t)(ks + colBofs) * 2);
                b[np*2][0] = q0; b[np*2][1] = q1;
                b[np*2+1][0] = q2; b[np*2+1][1] = q3;
            }
#pragma unroll
            for (int mi = 0; mi < 4; mi++)
#pragma unroll
                for (int ni = 0; ni < 4; ni++)
                    mma_bf16(d[mi][ni], a[mi], b[ni]);
        }
        __syncthreads();
    }

    // epilogue: + bias -> g_cb (bf16)
    const int cbase = bn + wn*32 + (lid & 3) * 2;
#pragma unroll
    for (int ni = 0; ni < 4; ni++) {
        const int col = cbase + ni*8;
        const float b0 = __ldg(bias + col), b1 = __ldg(bias + col + 1);
#pragma unroll
        for (int mi = 0; mi < 4; mi++) {
            const int r0 = bm + wm*64 + mi*16 + (lid >> 2);
            __nv_bfloat162 p0 = __floats2bfloat162_rn(d[mi][ni][0] + b0, d[mi][ni][1] + b1);
            __nv_bfloat162 p1 = __floats2bfloat162_rn(d[mi][ni][2] + b0, d[mi][ni][3] + b1);
            *(__nv_bfloat162*)(g_cb + (size_t)r0 * C_DIM + col)       = p0;
            *(__nv_bfloat162*)(g_cb + (size_t)(r0 + 8) * C_DIM + col) = p1;
        }
    }
}

// ---------------------------------------------------------------------------
// Scan + exact refinement: winner per row from approx bf16 c, fp32-verified.
// One warp per row; candidates = all j with c~_j >= max - margin.
// ---------------------------------------------------------------------------
__global__ void __launch_bounds__(256)
scan_refine(const float* __restrict__ w, const float* __restrict__ b)
{
    __shared__ int cnt[8];
    __shared__ int cand[8][64];
    const int wid = threadIdx.x >> 5, lid = threadIdx.x & 31;
    const int row = blockIdx.x * 8 + wid;

    const __nv_bfloat16* crow = g_cb + (size_t)row * C_DIM;
    float mx = -1e30f;
#pragma unroll
    for (int it = 0; it < 16; it++) {
        __nv_bfloat162 p = *(const __nv_bfloat162*)(crow + 2*(lid + it*32));
        mx = fmaxf(mx, fmaxf(__bfloat162float(p.x), __bfloat162float(p.y)));
    }
#pragma unroll
    for (int off = 16; off > 0; off >>= 1)
        mx = fmaxf(mx, __shfl_xor_sync(0xffffffffu, mx, off));

    float margin = 0.06f * fabsf(mx) + 1e-5f;
    float thr = mx - margin;
    if (lid == 0) cnt[wid] = 0;
    __syncwarp();
#pragma unroll
    for (int it = 0; it < 16; it++) {
        int j0 = 2*(lid + it*32);
        __nv_bfloat162 p = *(const __nv_bfloat162*)(crow + j0);
        if (__bfloat162float(p.x) >= thr) {
            int q = atomicAdd(&cnt[wid], 1);
            if (q < 64) cand[wid][q] = j0;
        }
        if (__bfloat162float(p.y) >= thr) {
            int q = atomicAdd(&cnt[wid], 1);
            if (q < 64) cand[wid][q] = j0 + 1;
        }
    }
    __syncwarp();
    int n = min(cnt[wid], 64);

    const float* hrow = g_h + (size_t)row * H_DIM;
    float best = -1e30f; int bidx = C_DIM;
    for (int ci = 0; ci < n; ci++) {
        int j = cand[wid][ci];
        const float* wr = w + (size_t)j * H_DIM;
        float s = 0.0f;
#pragma unroll
        for (int i = 0; i < 16; i++) {
            int k = lid + i * 32;
            s = fmaf(hrow[k], wr[k], s);
        }
#pragma unroll
        for (int off = 16; off > 0; off >>= 1)
            s += __shfl_xor_sync(0xffffffffu, s, off);
        s += b[j];
        if (s > best || (s == best && j < bidx)) { best = s; bidx = j; }
    }
    if (lid == 0) g_widx[row] = bidx;
}

// table[c, o] = log_softmax_o(h2o_w[o, c] + h2o_b[o]); shuffle reductions.
__global__ void build_table(const float* __restrict__ w, const float* __restrict__ b)
{
    __shared__ float wred[16];
    __shared__ float wsum[16];
    const int c = blockIdx.x, o = threadIdx.x;
    const int lw = o >> 5, lid = o & 31;
    float v = w[(size_t)o * C_DIM + c] + b[o];

    float m = v;
#pragma unroll
    for (int off = 16; off > 0; off >>= 1)
        m = fmaxf(m, __shfl_xor_sync(0xffffffffu, m, off));
    if (lid == 0) wred[lw] = m;
    __syncthreads();
    float mx = wred[0];
#pragma unroll
    for (int i = 1; i < 16; i++) mx = fmaxf(mx, wred[i]);

    float e = expf(v - mx);
    float s = e;
#pragma unroll
    for (int off = 16; off > 0; off >>= 1)
        s += __shfl_xor_sync(0xffffffffu, s, off);
    if (lid == 0) wsum[lw] = s;
    __syncthreads();
    float tot = 0.0f;
#pragma unroll
    for (int i = 0; i < 16; i++) tot += wsum[i];

    g_table[(size_t)c * O_DIM + o] = v - (logf(tot) + mx);
}

__global__ void gather_out(float* __restrict__ out)
{
    int row = blockIdx.x;
    int c = g_widx[row];
    const float4* src = (const float4*)(g_table + (size_t)c * O_DIM);
    float4* dst = (float4*)(out + (size_t)row * O_DIM);
    dst[threadIdx.x] = src[threadIdx.x];
}

extern "C" void kernel_launch(void* const* d_in, const int* in_sizes, int n_in,
                              void* d_out, int out_size)
{
    const float* x     = (const float*)d_in[0];
    const float* i2m_w = (const float*)d_in[2];
    const float* i2m_b = (const float*)d_in[3];
    const float* m2h_w = (const float*)d_in[4];
    const float* m2h_b = (const float*)d_in[5];
    const float* h2o_w = (const float*)d_in[6];
    const float* h2o_b = (const float*)d_in[7];
    float* out = (float*)d_out;

    // 1) h = relu(x @ i2m_w^T + b)  (fp32 exact via FFMA2 + bf16 copy)
    gemm1<<<dim3(H_DIM/128, ROWS/128), 256>>>(x, i2m_w, i2m_b);

    // weight conversion (independent of gemm1)
    conv_w2<<<(C_DIM*H_DIM/4)/256, 256>>>(m2h_w);

    // 2) approx c = h_bf16 @ w_bf16^T + b  via HMMA mma.sync -> bf16
    gemm2_mma<<<dim3(C_DIM/128, ROWS/128), 256>>>(m2h_b);

    // 3) winner per row, fp32-verified
    scan_refine<<<ROWS/8, 256>>>(m2h_w, m2h_b);

    // 4) log_softmax table + 5) gather
    build_table<<<C_DIM, O_DIM>>>(h2o_w, h2o_b);
    gather_out<<<ROWS, O_DIM/4>>>(out);
}

// round 5
// speedup vs baseline: 2.6615x; 1.0372x over previous
#include <cuda_runtime.h>
#include <cuda_bf16.h>
#include <stdint.h>

// Problem dims
#define ROWS   32768          // T*B
#define I_DIM  256
#define H_DIM  512
#define C_DIM  1024
#define O_DIM  512

// Scratch (device globals: no allocation allowed)
__device__ float         g_h[(size_t)ROWS * H_DIM];     // fp32 hidden (fp32-grade exact)
__device__ __nv_bfloat16 g_hb[(size_t)ROWS * H_DIM];    // bf16 hidden
__device__ __nv_bfloat16 g_w2b[(size_t)C_DIM * H_DIM];  // bf16 m2h_w
__device__ __nv_bfloat16 g_cb[(size_t)ROWS * C_DIM];    // approx concept pre-acts (bf16)
__device__ float         g_table[(size_t)C_DIM * O_DIM];// log_softmax table

// bf16 splits of x [ROWS, I_DIM] and i2m_w [H_DIM, I_DIM]
__device__ __nv_bfloat16 g_x1[(size_t)ROWS * I_DIM];
__device__ __nv_bfloat16 g_x2[(size_t)ROWS * I_DIM];
__device__ __nv_bfloat16 g_x3[(size_t)ROWS * I_DIM];
__device__ __nv_bfloat16 g_v1[(size_t)H_DIM * I_DIM];
__device__ __nv_bfloat16 g_v2[(size_t)H_DIM * I_DIM];
__device__ __nv_bfloat16 g_v3[(size_t)H_DIM * I_DIM];

// ---------------------------------------------------------------------------
// PTX helpers (base sm_103 ISA: cp.async / ldmatrix / mma.sync)
// ---------------------------------------------------------------------------
__device__ __forceinline__ uint32_t smem_u32(const void* p) {
    uint32_t a;
    asm("{ .reg .u64 t; cvta.to.shared.u64 t, %1; cvt.u32.u64 %0, t; }" : "=r"(a) : "l"(p));
    return a;
}
#define CP_ASYNC16(dst, src) \
    asm volatile("cp.async.cg.shared.global [%0], [%1], 16;" :: "r"(dst), "l"(src) : "memory")
#define CP_COMMIT()  asm volatile("cp.async.commit_group;" ::: "memory")
#define CP_WAIT(n)   asm volatile("cp.async.wait_group %0;" :: "n"(n) : "memory")

__device__ __forceinline__ void ldsm_x4(uint32_t& r0, uint32_t& r1, uint32_t& r2, uint32_t& r3,
                                        uint32_t addr) {
    asm volatile("ldmatrix.sync.aligned.m8n8.x4.shared.b16 {%0,%1,%2,%3}, [%4];"
                 : "=r"(r0), "=r"(r1), "=r"(r2), "=r"(r3) : "r"(addr));
}
__device__ __forceinline__ void mma_bf16(float* d, const uint32_t* a, const uint32_t* b) {
    asm volatile("mma.sync.aligned.m16n8k16.row.col.f32.bf16.bf16.f32 "
                 "{%0,%1,%2,%3}, {%4,%5,%6,%7}, {%8,%9}, {%0,%1,%2,%3};"
                 : "+f"(d[0]), "+f"(d[1]), "+f"(d[2]), "+f"(d[3])
                 : "r"(a[0]), "r"(a[1]), "r"(a[2]), "r"(a[3]), "r"(b[0]), "r"(b[1]));
}

// ---------------------------------------------------------------------------
// split kernels: fp32 -> 3-way bf16 split (x = x1 + x2 + x3, residual 2^-27)
// ---------------------------------------------------------------------------
__device__ __forceinline__ void split3(float v, __nv_bfloat16& a, __nv_bfloat16& b,
                                       __nv_bfloat16& c) {
    a = __float2bfloat16(v);
    float r1 = v - __bfloat162float(a);
    b = __float2bfloat16(r1);
    float r2 = r1 - __bfloat162float(b);
    c = __float2bfloat16(r2);
}

__global__ void split_x(const float* __restrict__ x)
{
    size_t i = (size_t)blockIdx.x * 256 + threadIdx.x;   // over ROWS*I_DIM/4 float4s
    float4 v = *(const float4*)(x + i * 4);
    __nv_bfloat16 a[4], b[4], c[4];
    split3(v.x, a[0], b[0], c[0]);
    split3(v.y, a[1], b[1], c[1]);
    split3(v.z, a[2], b[2], c[2]);
    split3(v.w, a[3], b[3], c[3]);
    *(uint2*)(g_x1 + i * 4) = *(uint2*)a;
    *(uint2*)(g_x2 + i * 4) = *(uint2*)b;
    *(uint2*)(g_x3 + i * 4) = *(uint2*)c;
}

__global__ void split_w1(const float* __restrict__ w)
{
    size_t i = (size_t)blockIdx.x * 256 + threadIdx.x;   // over H_DIM*I_DIM/4
    float4 v = *(const float4*)(w + i * 4);
    __nv_bfloat16 a[4], b[4], c[4];
    split3(v.x, a[0], b[0], c[0]);
    split3(v.y, a[1], b[1], c[1]);
    split3(v.z, a[2], b[2], c[2]);
    split3(v.w, a[3], b[3], c[3]);
    *(uint2*)(g_v1 + i * 4) = *(uint2*)a;
    *(uint2*)(g_v2 + i * 4) = *(uint2*)b;
    *(uint2*)(g_v3 + i * 4) = *(uint2*)c;
}

// convert m2h_w (fp32 [C,H]) -> bf16
__global__ void conv_w2(const float* __restrict__ w)
{
    size_t i = (size_t)blockIdx.x * 256 + threadIdx.x;   // over C*H/4 float4s
    float4 v = *(const float4*)(w + i * 4);
    __nv_bfloat16 b[4] = { __float2bfloat16(v.x), __float2bfloat16(v.y),
                           __float2bfloat16(v.z), __float2bfloat16(v.w) };
    *(uint2*)(g_w2b + i * 4) = *(uint2*)b;
}

// ---------------------------------------------------------------------------
// GEMM1 via bf16x6 HMMA (fp32-exact): g_h = relu(x @ i2m_w^T + b), + bf16 copy.
// 6 accumulating K=256 passes over split pairs; block 128x128, BK=32, 2-stage.
// ---------------------------------------------------------------------------
#define BK        32
#define SROW      40                      // padded row length (bf16 elems)
#define STAGE_B   (128 * SROW * 2)        // bytes per stage buffer (10240)

__global__ void __launch_bounds__(256)
gemm1_mma(const float* __restrict__ bias)
{
    __shared__ __align__(16) __nv_bfloat16 As[2][128 * SROW];
    __shared__ __align__(16) __nv_bfloat16 Bs[2][128 * SROW];

    const int t   = threadIdx.x;
    const int wid = t >> 5, lid = t & 31;
    const int wm  = wid & 1;
    const int wn  = wid >> 1;
    const int bm  = blockIdx.y * 128, bn = blockIdx.x * 128;

    const __nv_bfloat16* Aps[6] = { g_x1, g_x1, g_x2, g_x1, g_x2, g_x3 };
    const __nv_bfloat16* Bps[6] = { g_v1, g_v2, g_v1, g_v3, g_v2, g_v1 };

    const uint32_t sA = smem_u32(As);
    const uint32_t sB = smem_u32(Bs);

    const int r0l = t >> 2,         s0 = (t & 3);
    const int r1l = (t + 256) >> 2, s1 = (t & 3);

    float d[4][4][4];
#pragma unroll
    for (int mi = 0; mi < 4; mi++)
#pragma unroll
        for (int ni = 0; ni < 4; ni++)
#pragma unroll
            for (int r = 0; r < 4; r++) d[mi][ni][r] = 0.0f;

    // prefetch stage 0 (seg 0, k0 = 0)
    {
        const __nv_bfloat16* Ap = Aps[0];
        const __nv_bfloat16* Bp = Bps[0];
        CP_ASYNC16(sA + r0l*80 + s0*16, Ap + (size_t)(bm + r0l)*I_DIM + s0*8);
        CP_ASYNC16(sB + r0l*80 + s0*16, Bp + (size_t)(bn + r0l)*I_DIM + s0*8);
        CP_ASYNC16(sA + r1l*80 + s1*16, Ap + (size_t)(bm + r1l)*I_DIM + s1*8);
        CP_ASYNC16(sB + r1l*80 + s1*16, Bp + (size_t)(bn + r1l)*I_DIM + s1*8);
        CP_COMMIT();
    }

    const int rowA = wm*64 + (lid & 15);
    const int colAofs = (lid < 16) ? 0 : 8;
    const int rowB = wn*32 + ((lid >> 4) & 1)*8 + (lid & 7);
    const int colBofs = ((lid >> 3) & 1)*8;

    const int NIT = 6 * (I_DIM / BK);     // 48 iterations
    for (int kt = 0; kt < NIT; kt++) {
        const int buf = kt & 1;
        if (kt + 1 < NIT) {
            const int seg = (kt + 1) >> 3;
            const int k0  = ((kt + 1) & 7) * BK;
            const __nv_bfloat16* Ap = Aps[seg];
            const __nv_bfloat16* Bp = Bps[seg];
            const uint32_t dA = sA + (1 - buf) * STAGE_B;
            const uint32_t dB = sB + (1 - buf) * STAGE_B;
            CP_ASYNC16(dA + r0l*80 + s0*16, Ap + (size_t)(bm + r0l)*I_DIM + k0 + s0*8);
            CP_ASYNC16(dB + r0l*80 + s0*16, Bp + (size_t)(bn + r0l)*I_DIM + k0 + s0*8);
            CP_ASYNC16(dA + r1l*80 + s1*16, Ap + (size_t)(bm + r1l)*I_DIM + k0 + s1*8);
            CP_ASYNC16(dB + r1l*80 + s1*16, Bp + (size_t)(bn + r1l)*I_DIM + k0 + s1*8);
            CP_COMMIT();
            CP_WAIT(1);
        } else {
            CP_WAIT(0);
        }
        __syncthreads();

        const uint32_t aB = sA + buf * STAGE_B;
        const uint32_t bB = sB + buf * STAGE_B;
#pragma unroll
        for (int ks = 0; ks < BK; ks += 16) {
            uint32_t a[4][4];
#pragma unroll
            for (int mi = 0; mi < 4; mi++)
                ldsm_x4(a[mi][0], a[mi][1], a[mi][2], a[mi][3],
                        aB + (uint32_t)(rowA + mi*16) * 80 + (uint32_t)(ks + colAofs) * 2);
            uint32_t b[4][2];
#pragma unroll
            for (int np = 0; np < 2; np++) {
                uint32_t q0, q1, q2, q3;
                ldsm_x4(q0, q1, q2, q3,
                        bB + (uint32_t)(rowB + np*16) * 80 + (uint32_t)(ks + colBofs) * 2);
                b[np*2][0] = q0; b[np*2][1] = q1;
                b[np*2+1][0] = q2; b[np*2+1][1] = q3;
            }
#pragma unroll
            for (int mi = 0; mi < 4; mi++)
#pragma unroll
                for (int ni = 0; ni < 4; ni++)
                    mma_bf16(d[mi][ni], a[mi], b[ni]);
        }
        __syncthreads();
    }

    // epilogue: + bias, relu -> g_h (fp32) and g_hb (bf16)
    const int cbase = bn + wn*32 + (lid & 3) * 2;
#pragma unroll
    for (int ni = 0; ni < 4; ni++) {
        const int col = cbase + ni*8;
        const float b0 = __ldg(bias + col), b1 = __ldg(bias + col + 1);
#pragma unroll
        for (int mi = 0; mi < 4; mi++) {
            const int r0 = bm + wm*64 + mi*16 + (lid >> 2);
            float v00 = fmaxf(d[mi][ni][0] + b0, 0.0f);
            float v01 = fmaxf(d[mi][ni][1] + b1, 0.0f);
            float v10 = fmaxf(d[mi][ni][2] + b0, 0.0f);
            float v11 = fmaxf(d[mi][ni][3] + b1, 0.0f);
            *(float2*)(g_h + (size_t)r0 * H_DIM + col)       = make_float2(v00, v01);
            *(float2*)(g_h + (size_t)(r0 + 8) * H_DIM + col) = make_float2(v10, v11);
            *(__nv_bfloat162*)(g_hb + (size_t)r0 * H_DIM + col) =
                __floats2bfloat162_rn(v00, v01);
            *(__nv_bfloat162*)(g_hb + (size_t)(r0 + 8) * H_DIM + col) =
                __floats2bfloat162_rn(v10, v11);
        }
    }
}

// ---------------------------------------------------------------------------
// GEMM2 via mma.sync (HMMA bf16, fp32 accum): g_cb = bf16(g_hb @ g_w2b^T + b)
// ---------------------------------------------------------------------------
__global__ void __launch_bounds__(256)
gemm2_mma(const float* __restrict__ bias)
{
    __shared__ __align__(16) __nv_bfloat16 As[2][128 * SROW];
    __shared__ __align__(16) __nv_bfloat16 Bs[2][128 * SROW];

    const int t   = threadIdx.x;
    const int wid = t >> 5, lid = t & 31;
    const int wm  = wid & 1;
    const int wn  = wid >> 1;
    const int bm  = blockIdx.y * 128, bn = blockIdx.x * 128;

    const uint32_t sA = smem_u32(As);
    const uint32_t sB = smem_u32(Bs);

    const int r0l = t >> 2,         s0 = (t & 3);
    const int r1l = (t + 256) >> 2, s1 = (t & 3);

    float d[4][4][4];
#pragma unroll
    for (int mi = 0; mi < 4; mi++)
#pragma unroll
        for (int ni = 0; ni < 4; ni++)
#pragma unroll
            for (int r = 0; r < 4; r++) d[mi][ni][r] = 0.0f;

    {
        CP_ASYNC16(sA + r0l*80 + s0*16, g_hb  + (size_t)(bm + r0l)*H_DIM + s0*8);
        CP_ASYNC16(sB + r0l*80 + s0*16, g_w2b + (size_t)(bn + r0l)*H_DIM + s0*8);
        CP_ASYNC16(sA + r1l*80 + s1*16, g_hb  + (size_t)(bm + r1l)*H_DIM + s1*8);
        CP_ASYNC16(sB + r1l*80 + s1*16, g_w2b + (size_t)(bn + r1l)*H_DIM + s1*8);
        CP_COMMIT();
    }

    const int rowA = wm*64 + (lid & 15);
    const int colAofs = (lid < 16) ? 0 : 8;
    const int rowB = wn*32 + ((lid >> 4) & 1)*8 + (lid & 7);
    const int colBofs = ((lid >> 3) & 1)*8;

    const int NIT = H_DIM / BK;           // 16
    for (int kt = 0; kt < NIT; kt++) {
        const int buf = kt & 1;
        if (kt + 1 < NIT) {
            const int k0 = (kt + 1) * BK;
            const uint32_t dA = sA + (1 - buf) * STAGE_B;
            const uint32_t dB = sB + (1 - buf) * STAGE_B;
            CP_ASYNC16(dA + r0l*80 + s0*16, g_hb  + (size_t)(bm + r0l)*H_DIM + k0 + s0*8);
            CP_ASYNC16(dB + r0l*80 + s0*16, g_w2b + (size_t)(bn + r0l)*H_DIM + k0 + s0*8);
            CP_ASYNC16(dA + r1l*80 + s1*16, g_hb  + (size_t)(bm + r1l)*H_DIM + k0 + s1*8);
            CP_ASYNC16(dB + r1l*80 + s1*16, g_w2b + (size_t)(bn + r1l)*H_DIM + k0 + s1*8);
            CP_COMMIT();
            CP_WAIT(1);
        } else {
            CP_WAIT(0);
        }
        __syncthreads();

        const uint32_t aB = sA + buf * STAGE_B;
        const uint32_t bB = sB + buf * STAGE_B;
#pragma unroll
        for (int ks = 0; ks < BK; ks += 16) {
            uint32_t a[4][4];
#pragma unroll
            for (int mi = 0; mi < 4; mi++)
                ldsm_x4(a[mi][0], a[mi][1], a[mi][2], a[mi][3],
                        aB + (uint32_t)(rowA + mi*16) * 80 + (uint32_t)(ks + colAofs) * 2);
            uint32_t b[4][2];
#pragma unroll
            for (int np = 0; np < 2; np++) {
                uint32_t q0, q1, q2, q3;
                ldsm_x4(q0, q1, q2, q3,
                        bB + (uint32_t)(rowB + np*16) * 80 + (uint32_t)(ks + colBofs) * 2);
                b[np*2][0] = q0; b[np*2][1] = q1;
                b[np*2+1][0] = q2; b[np*2+1][1] = q3;
            }
#pragma unroll
            for (int mi = 0; mi < 4; mi++)
#pragma unroll
                for (int ni = 0; ni < 4; ni++)
                    mma_bf16(d[mi][ni], a[mi], b[ni]);
        }
        __syncthreads();
    }

    const int cbase = bn + wn*32 + (lid & 3) * 2;
#pragma unroll
    for (int ni = 0; ni < 4; ni++) {
        const int col = cbase + ni*8;
        const float b0 = __ldg(bias + col), b1 = __ldg(bias + col + 1);
#pragma unroll
        for (int mi = 0; mi < 4; mi++) {
            const int r0 = bm + wm*64 + mi*16 + (lid >> 2);
            __nv_bfloat162 p0 = __floats2bfloat162_rn(d[mi][ni][0] + b0, d[mi][ni][1] + b1);
            __nv_bfloat162 p1 = __floats2bfloat162_rn(d[mi][ni][2] + b0, d[mi][ni][3] + b1);
            *(__nv_bfloat162*)(g_cb + (size_t)r0 * C_DIM + col)       = p0;
            *(__nv_bfloat162*)(g_cb + (size_t)(r0 + 8) * C_DIM + col) = p1;
        }
    }
}

// table[c, o] = log_softmax_o(h2o_w[o, c] + h2o_b[o]); shuffle reductions.
__global__ void build_table(const float* __restrict__ w, const float* __restrict__ b)
{
    __shared__ float wred[16];
    __shared__ float wsum[16];
    const int c = blockIdx.x, o = threadIdx.x;
    const int lw = o >> 5, lid = o & 31;
    float v = w[(size_t)o * C_DIM + c] + b[o];

    float m = v;
#pragma unroll
    for (int off = 16; off > 0; off >>= 1)
        m = fmaxf(m, __shfl_xor_sync(0xffffffffu, m, off));
    if (lid == 0) wred[lw] = m;
    __syncthreads();
    float mx = wred[0];
#pragma unroll
    for (int i = 1; i < 16; i++) mx = fmaxf(mx, wred[i]);

    float e = expf(v - mx);
    float s = e;
#pragma unroll
    for (int off = 16; off > 0; off >>= 1)
        s += __shfl_xor_sync(0xffffffffu, s, off);
    if (lid == 0) wsum[lw] = s;
    __syncthreads();
    float tot = 0.0f;
#pragma unroll
    for (int i = 0; i < 16; i++) tot += wsum[i];

    g_table[(size_t)c * O_DIM + o] = v - (logf(tot) + mx);
}

// ---------------------------------------------------------------------------
// Scan + exact refinement + output write. One warp per row.
// ---------------------------------------------------------------------------
__global__ void __launch_bounds__(256)
scan_out(const float* __restrict__ w, const float* __restrict__ b,
         float* __restrict__ out)
{
    __shared__ int cnt[8];
    __shared__ int cand[8][64];
    const int wid = threadIdx.x >> 5, lid = threadIdx.x & 31;
    const int row = blockIdx.x * 8 + wid;

    const __nv_bfloat16* crow = g_cb + (size_t)row * C_DIM;
    float mx = -1e30f;
#pragma unroll
    for (int it = 0; it < 16; it++) {
        __nv_bfloat162 p = *(const __nv_bfloat162*)(crow + 2*(lid + it*32));
        mx = fmaxf(mx, fmaxf(__bfloat162float(p.x), __bfloat162float(p.y)));
    }
#pragma unroll
    for (int off = 16; off > 0; off >>= 1)
        mx = fmaxf(mx, __shfl_xor_sync(0xffffffffu, mx, off));

    float margin = 0.06f * fabsf(mx) + 1e-5f;
    float thr = mx - margin;
    if (lid == 0) cnt[wid] = 0;
    __syncwarp();
#pragma unroll
    for (int it = 0; it < 16; it++) {
        int j0 = 2*(lid + it*32);
        __nv_bfloat162 p = *(const __nv_bfloat162*)(crow + j0);
        if (__bfloat162float(p.x) >= thr) {
            int q = atomicAdd(&cnt[wid], 1);
            if (q < 64) cand[wid][q] = j0;
        }
        if (__bfloat162float(p.y) >= thr) {
            int q = atomicAdd(&cnt[wid], 1);
            if (q < 64) cand[wid][q] = j0 + 1;
        }
    }
    __syncwarp();
    int n = min(cnt[wid], 64);

    const float* hrow = g_h + (size_t)row * H_DIM;
    float best = -1e30f; int bidx = C_DIM;
    for (int ci = 0; ci < n; ci++) {
        int j = cand[wid][ci];
        const float* wr = w + (size_t)j * H_DIM;
        float s = 0.0f;
#pragma unroll
        for (int i = 0; i < 16; i++) {
            int k = lid + i * 32;
            s = fmaf(hrow[k], wr[k], s);
        }
#pragma unroll
        for (int off = 16; off > 0; off >>= 1)
            s += __shfl_xor_sync(0xffffffffu, s, off);
        s += b[j];
        if (s > best || (s == best && j < bidx)) { best = s; bidx = j; }
    }
    // broadcast winner and write output row directly from the table
    bidx = __shfl_sync(0xffffffffu, bidx, 0);
    const float4* src = (const float4*)(g_table + (size_t)bidx * O_DIM);
    float4* dst = (float4*)(out + (size_t)row * O_DIM);
#pragma unroll
    for (int i = 0; i < 4; i++)
        dst[lid + i * 32] = src[lid + i * 32];
}

extern "C" void kernel_launch(void* const* d_in, const int* in_sizes, int n_in,
                              void* d_out, int out_size)
{
    const float* x     = (const float*)d_in[0];
    const float* i2m_w = (const float*)d_in[2];
    const float* i2m_b = (const float*)d_in[3];
    const float* m2h_w = (const float*)d_in[4];
    const float* m2h_b = (const float*)d_in[5];
    const float* h2o_w = (const float*)d_in[6];
    const float* h2o_b = (const float*)d_in[7];
    float* out = (float*)d_out;

    // prep: splits + conversions + table (all independent)
    split_x<<<(ROWS*I_DIM/4)/256, 256>>>(x);
    split_w1<<<(H_DIM*I_DIM/4)/256, 256>>>(i2m_w);
    conv_w2<<<(C_DIM*H_DIM/4)/256, 256>>>(m2h_w);
    build_table<<<C_DIM, O_DIM>>>(h2o_w, h2o_b);

    // 1) h = relu(x @ i2m_w^T + b)  (bf16x6 exact on tensor cores)
    gemm1_mma<<<dim3(H_DIM/128, ROWS/128), 256>>>(i2m_b);

    // 2) approx c = h_bf16 @ w_bf16^T + b  -> bf16
    gemm2_mma<<<dim3(C_DIM/128, ROWS/128), 256>>>(m2h_b);

    // 3) winner per row (fp32-verified) + output write
    scan_out<<<ROWS/8, 256>>>(m2h_w, m2h_b, out);
}

// round 6
// speedup vs baseline: 2.9816x; 1.1203x over previous
#include <cuda_runtime.h>
#include <cuda_bf16.h>
#include <stdint.h>

// Problem dims
#define ROWS   32768          // T*B
#define I_DIM  256
#define H_DIM  512
#define C_DIM  1024
#define O_DIM  512

// Scratch (device globals: no allocation allowed)
__device__ float         g_h[(size_t)ROWS * H_DIM];     // fp32 hidden (fp32-grade exact)
__device__ __nv_bfloat16 g_hb[(size_t)ROWS * H_DIM];    // bf16 hidden
__device__ __nv_bfloat16 g_w2b[(size_t)C_DIM * H_DIM];  // bf16 m2h_w
__device__ __nv_bfloat16 g_cb[(size_t)ROWS * C_DIM];    // approx concept pre-acts (bf16)
__device__ float         g_table[(size_t)C_DIM * O_DIM];// log_softmax table

// bf16 splits of x [ROWS, I_DIM] and i2m_w [H_DIM, I_DIM]
__device__ __nv_bfloat16 g_x1[(size_t)ROWS * I_DIM];
__device__ __nv_bfloat16 g_x2[(size_t)ROWS * I_DIM];
__device__ __nv_bfloat16 g_x3[(size_t)ROWS * I_DIM];
__device__ __nv_bfloat16 g_v1[(size_t)H_DIM * I_DIM];
__device__ __nv_bfloat16 g_v2[(size_t)H_DIM * I_DIM];
__device__ __nv_bfloat16 g_v3[(size_t)H_DIM * I_DIM];

// ---------------------------------------------------------------------------
// PTX helpers (base sm_103 ISA: cp.async / ldmatrix / mma.sync)
// ---------------------------------------------------------------------------
__device__ __forceinline__ uint32_t smem_u32(const void* p) {
    uint32_t a;
    asm("{ .reg .u64 t; cvta.to.shared.u64 t, %1; cvt.u32.u64 %0, t; }" : "=r"(a) : "l"(p));
    return a;
}
#define CP_ASYNC16(dst, src) \
    asm volatile("cp.async.cg.shared.global [%0], [%1], 16;" :: "r"(dst), "l"(src) : "memory")
#define CP_COMMIT()  asm volatile("cp.async.commit_group;" ::: "memory")
#define CP_WAIT(n)   asm volatile("cp.async.wait_group %0;" :: "n"(n) : "memory")

__device__ __forceinline__ void ldsm_x4(uint32_t& r0, uint32_t& r1, uint32_t& r2, uint32_t& r3,
                                        uint32_t addr) {
    asm volatile("ldmatrix.sync.aligned.m8n8.x4.shared.b16 {%0,%1,%2,%3}, [%4];"
                 : "=r"(r0), "=r"(r1), "=r"(r2), "=r"(r3) : "r"(addr));
}
__device__ __forceinline__ void mma_bf16(float* d, const uint32_t* a, const uint32_t* b) {
    asm volatile("mma.sync.aligned.m16n8k16.row.col.f32.bf16.bf16.f32 "
                 "{%0,%1,%2,%3}, {%4,%5,%6,%7}, {%8,%9}, {%0,%1,%2,%3};"
                 : "+f"(d[0]), "+f"(d[1]), "+f"(d[2]), "+f"(d[3])
                 : "r"(a[0]), "r"(a[1]), "r"(a[2]), "r"(a[3]), "r"(b[0]), "r"(b[1]));
}

// ---------------------------------------------------------------------------
// split kernels: fp32 -> 3-way bf16 split (x = x1 + x2 + x3, residual 2^-27)
// ---------------------------------------------------------------------------
__device__ __forceinline__ void split3(float v, __nv_bfloat16& a, __nv_bfloat16& b,
                                       __nv_bfloat16& c) {
    a = __float2bfloat16(v);
    float r1 = v - __bfloat162float(a);
    b = __float2bfloat16(r1);
    float r2 = r1 - __bfloat162float(b);
    c = __float2bfloat16(r2);
}

__global__ void split_x(const float* __restrict__ x)
{
    size_t i = (size_t)blockIdx.x * 256 + threadIdx.x;
    float4 v = *(const float4*)(x + i * 4);
    __nv_bfloat16 a[4], b[4], c[4];
    split3(v.x, a[0], b[0], c[0]);
    split3(v.y, a[1], b[1], c[1]);
    split3(v.z, a[2], b[2], c[2]);
    split3(v.w, a[3], b[3], c[3]);
    *(uint2*)(g_x1 + i * 4) = *(uint2*)a;
    *(uint2*)(g_x2 + i * 4) = *(uint2*)b;
    *(uint2*)(g_x3 + i * 4) = *(uint2*)c;
}

__global__ void split_w1(const float* __restrict__ w)
{
    size_t i = (size_t)blockIdx.x * 256 + threadIdx.x;
    float4 v = *(const float4*)(w + i * 4);
    __nv_bfloat16 a[4], b[4], c[4];
    split3(v.x, a[0], b[0], c[0]);
    split3(v.y, a[1], b[1], c[1]);
    split3(v.z, a[2], b[2], c[2]);
    split3(v.w, a[3], b[3], c[3]);
    *(uint2*)(g_v1 + i * 4) = *(uint2*)a;
    *(uint2*)(g_v2 + i * 4) = *(uint2*)b;
    *(uint2*)(g_v3 + i * 4) = *(uint2*)c;
}

// convert m2h_w (fp32 [C,H]) -> bf16
__global__ void conv_w2(const float* __restrict__ w)
{
    size_t i = (size_t)blockIdx.x * 256 + threadIdx.x;
    float4 v = *(const float4*)(w + i * 4);
    __nv_bfloat16 b[4] = { __float2bfloat16(v.x), __float2bfloat16(v.y),
                           __float2bfloat16(v.z), __float2bfloat16(v.w) };
    *(uint2*)(g_w2b + i * 4) = *(uint2*)b;
}

// ---------------------------------------------------------------------------
// Pipelined HMMA GEMM core constants
// 128x128 block, 8 warps (2x4), warp tile 64x32, BK=32, 5-stage cp.async.
// ---------------------------------------------------------------------------
#define BK        32
#define SROW      40                      // padded row length (bf16 elems) = 80B
#define STAGE_HB  (128 * SROW * 2)        // bytes per half-stage (A or B) = 10240
#define STAGE_SZ  (2 * STAGE_HB)          // 20480
#define STAGES    5
#define SMEM_DYN  (STAGES * STAGE_SZ)     // 102400

// ---------------------------------------------------------------------------
// GEMM1 via bf16x6 HMMA (fp32-exact): g_h = relu(x @ i2m_w^T + b), + bf16 copy.
// 6 accumulating K=256 passes over split pairs. NIT = 48.
// ---------------------------------------------------------------------------
__global__ void __launch_bounds__(256, 2)
gemm1_mma(const float* __restrict__ bias)
{
    extern __shared__ __align__(16) unsigned char smem[];

    const int t   = threadIdx.x;
    const int wid = t >> 5, lid = t & 31;
    const int wm  = wid & 1;
    const int wn  = wid >> 1;
    const int bm  = blockIdx.y * 128, bn = blockIdx.x * 128;

    const __nv_bfloat16* Aps[6] = { g_x1, g_x1, g_x2, g_x1, g_x2, g_x3 };
    const __nv_bfloat16* Bps[6] = { g_v1, g_v2, g_v1, g_v3, g_v2, g_v1 };

    const uint32_t sbase = smem_u32(smem);

    const int r0l = t >> 2,         s0 = (t & 3);
    const int r1l = (t + 256) >> 2, s1 = (t & 3);

    float d[4][4][4];
#pragma unroll
    for (int mi = 0; mi < 4; mi++)
#pragma unroll
        for (int ni = 0; ni < 4; ni++)
#pragma unroll
            for (int r = 0; r < 4; r++) d[mi][ni][r] = 0.0f;

    const int NIT = 6 * (I_DIM / BK);     // 48

    // prologue: prefetch stages for kt = 0..3
#pragma unroll
    for (int p = 0; p < STAGES - 1; p++) {
        const int seg = p >> 3;
        const int k0  = (p & 7) * BK;
        const __nv_bfloat16* Ap = Aps[seg];
        const __nv_bfloat16* Bp = Bps[seg];
        const uint32_t dA = sbase + p * STAGE_SZ;
        const uint32_t dB = dA + STAGE_HB;
        CP_ASYNC16(dA + r0l*80 + s0*16, Ap + (size_t)(bm + r0l)*I_DIM + k0 + s0*8);
        CP_ASYNC16(dB + r0l*80 + s0*16, Bp + (size_t)(bn + r0l)*I_DIM + k0 + s0*8);
        CP_ASYNC16(dA + r1l*80 + s1*16, Ap + (size_t)(bm + r1l)*I_DIM + k0 + s1*8);
        CP_ASYNC16(dB + r1l*80 + s1*16, Bp + (size_t)(bn + r1l)*I_DIM + k0 + s1*8);
        CP_COMMIT();
    }

    const int rowA = wm*64 + (lid & 15);
    const int colAofs = (lid < 16) ? 0 : 8;
    const int rowB = wn*32 + ((lid >> 4) & 1)*8 + (lid & 7);
    const int colBofs = ((lid >> 3) & 1)*8;

    int stage = 0;
    for (int kt = 0; kt < NIT; kt++) {
        CP_WAIT(STAGES - 2);
        __syncthreads();

        const uint32_t aB = sbase + stage * STAGE_SZ;
        const uint32_t bB = aB + STAGE_HB;
#pragma unroll
        for (int ks = 0; ks < BK; ks += 16) {
            uint32_t a[4][4];
#pragma unroll
            for (int mi = 0; mi < 4; mi++)
                ldsm_x4(a[mi][0], a[mi][1], a[mi][2], a[mi][3],
                        aB + (uint32_t)(rowA + mi*16) * 80 + (uint32_t)(ks + colAofs) * 2);
            uint32_t b[4][2];
#pragma unroll
            for (int np = 0; np < 2; np++) {
                uint32_t q0, q1, q2, q3;
                ldsm_x4(q0, q1, q2, q3,
                        bB + (uint32_t)(rowB + np*16) * 80 + (uint32_t)(ks + colBofs) * 2);
                b[np*2][0] = q0; b[np*2][1] = q1;
                b[np*2+1][0] = q2; b[np*2+1][1] = q3;
            }
#pragma unroll
            for (int mi = 0; mi < 4; mi++)
#pragma unroll
                for (int ni = 0; ni < 4; ni++)
                    mma_bf16(d[mi][ni], a[mi], b[ni]);
        }

        // prefetch kt + STAGES-1
        const int kn = kt + STAGES - 1;
        if (kn < NIT) {
            const int seg = kn >> 3;
            const int k0  = (kn & 7) * BK;
            const __nv_bfloat16* Ap = Aps[seg];
            const __nv_bfloat16* Bp = Bps[seg];
            const int ws = (stage + STAGES - 1) % STAGES;
            const uint32_t dA = sbase + ws * STAGE_SZ;
            const uint32_t dB = dA + STAGE_HB;
            CP_ASYNC16(dA + r0l*80 + s0*16, Ap + (size_t)(bm + r0l)*I_DIM + k0 + s0*8);
            CP_ASYNC16(dB + r0l*80 + s0*16, Bp + (size_t)(bn + r0l)*I_DIM + k0 + s0*8);
            CP_ASYNC16(dA + r1l*80 + s1*16, Ap + (size_t)(bm + r1l)*I_DIM + k0 + s1*8);
            CP_ASYNC16(dB + r1l*80 + s1*16, Bp + (size_t)(bn + r1l)*I_DIM + k0 + s1*8);
        }
        CP_COMMIT();

        stage = (stage + 1 == STAGES) ? 0 : stage + 1;
    }

    // epilogue: + bias, relu -> g_h (fp32) and g_hb (bf16)
    const int cbase = bn + wn*32 + (lid & 3) * 2;
#pragma unroll
    for (int ni = 0; ni < 4; ni++) {
        const int col = cbase + ni*8;
        const float b0 = __ldg(bias + col), b1 = __ldg(bias + col + 1);
#pragma unroll
        for (int mi = 0; mi < 4; mi++) {
            const int r0 = bm + wm*64 + mi*16 + (lid >> 2);
            float v00 = fmaxf(d[mi][ni][0] + b0, 0.0f);
            float v01 = fmaxf(d[mi][ni][1] + b1, 0.0f);
            float v10 = fmaxf(d[mi][ni][2] + b0, 0.0f);
            float v11 = fmaxf(d[mi][ni][3] + b1, 0.0f);
            *(float2*)(g_h + (size_t)r0 * H_DIM + col)       = make_float2(v00, v01);
            *(float2*)(g_h + (size_t)(r0 + 8) * H_DIM + col) = make_float2(v10, v11);
            *(__nv_bfloat162*)(g_hb + (size_t)r0 * H_DIM + col) =
                __floats2bfloat162_rn(v00, v01);
            *(__nv_bfloat162*)(g_hb + (size_t)(r0 + 8) * H_DIM + col) =
                __floats2bfloat162_rn(v10, v11);
        }
    }
}

// ---------------------------------------------------------------------------
// GEMM2 via mma.sync (HMMA bf16, fp32 accum): g_cb = bf16(g_hb @ g_w2b^T + b)
// NIT = 16, 5-stage pipeline.
// ---------------------------------------------------------------------------
__global__ void __launch_bounds__(256, 2)
gemm2_mma(const float* __restrict__ bias)
{
    extern __shared__ __align__(16) unsigned char smem[];

    const int t   = threadIdx.x;
    const int wid = t >> 5, lid = t & 31;
    const int wm  = wid & 1;
    const int wn  = wid >> 1;
    const int bm  = blockIdx.y * 128, bn = blockIdx.x * 128;

    const uint32_t sbase = smem_u32(smem);

    const int r0l = t >> 2,         s0 = (t & 3);
    const int r1l = (t + 256) >> 2, s1 = (t & 3);

    float d[4][4][4];
#pragma unroll
    for (int mi = 0; mi < 4; mi++)
#pragma unroll
        for (int ni = 0; ni < 4; ni++)
#pragma unroll
            for (int r = 0; r < 4; r++) d[mi][ni][r] = 0.0f;

    const int NIT = H_DIM / BK;           // 16

    // prologue: prefetch stages for kt = 0..3
#pragma unroll
    for (int p = 0; p < STAGES - 1; p++) {
        const int k0 = p * BK;
        const uint32_t dA = sbase + p * STAGE_SZ;
        const uint32_t dB = dA + STAGE_HB;
        CP_ASYNC16(dA + r0l*80 + s0*16, g_hb  + (size_t)(bm + r0l)*H_DIM + k0 + s0*8);
        CP_ASYNC16(dB + r0l*80 + s0*16, g_w2b + (size_t)(bn + r0l)*H_DIM + k0 + s0*8);
        CP_ASYNC16(dA + r1l*80 + s1*16, g_hb  + (size_t)(bm + r1l)*H_DIM + k0 + s1*8);
        CP_ASYNC16(dB + r1l*80 + s1*16, g_w2b + (size_t)(bn + r1l)*H_DIM + k0 + s1*8);
        CP_COMMIT();
    }

    const int rowA = wm*64 + (lid & 15);
    const int colAofs = (lid < 16) ? 0 : 8;
    const int rowB = wn*32 + ((lid >> 4) & 1)*8 + (lid & 7);
    const int colBofs = ((lid >> 3) & 1)*8;

    int stage = 0;
    for (int kt = 0; kt < NIT; kt++) {
        CP_WAIT(STAGES - 2);
        __syncthreads();

        const uint32_t aB = sbase + stage * STAGE_SZ;
        const uint32_t bB = aB + STAGE_HB;
#pragma unroll
        for (int ks = 0; ks < BK; ks += 16) {
            uint32_t a[4][4];
#pragma unroll
            for (int mi = 0; mi < 4; mi++)
                ldsm_x4(a[mi][0], a[mi][1], a[mi][2], a[mi][3],
                        aB + (uint32_t)(rowA + mi*16) * 80 + (uint32_t)(ks + colAofs) * 2);
            uint32_t b[4][2];
#pragma unroll
            for (int np = 0; np < 2; np++) {
                uint32_t q0, q1, q2, q3;
                ldsm_x4(q0, q1, q2, q3,
                        bB + (uint32_t)(rowB + np*16) * 80 + (uint32_t)(ks + colBofs) * 2);
                b[np*2][0] = q0; b[np*2][1] = q1;
                b[np*2+1][0] = q2; b[np*2+1][1] = q3;
            }
#pragma unroll
            for (int mi = 0; mi < 4; mi++)
#pragma unroll
                for (int ni = 0; ni < 4; ni++)
                    mma_bf16(d[mi][ni], a[mi], b[ni]);
        }

        const int kn = kt + STAGES - 1;
        if (kn < NIT) {
            const int k0 = kn * BK;
            const int ws = (stage + STAGES - 1) % STAGES;
            const uint32_t dA = sbase + ws * STAGE_SZ;
            const uint32_t dB = dA + STAGE_HB;
            CP_ASYNC16(dA + r0l*80 + s0*16, g_hb  + (size_t)(bm + r0l)*H_DIM + k0 + s0*8);
            CP_ASYNC16(dB + r0l*80 + s0*16, g_w2b + (size_t)(bn + r0l)*H_DIM + k0 + s0*8);
            CP_ASYNC16(dA + r1l*80 + s1*16, g_hb  + (size_t)(bm + r1l)*H_DIM + k0 + s1*8);
            CP_ASYNC16(dB + r1l*80 + s1*16, g_w2b + (size_t)(bn + r1l)*H_DIM + k0 + s1*8);
        }
        CP_COMMIT();

        stage = (stage + 1 == STAGES) ? 0 : stage + 1;
    }

    const int cbase = bn + wn*32 + (lid & 3) * 2;
#pragma unroll
    for (int ni = 0; ni < 4; ni++) {
        const int col = cbase + ni*8;
        const float b0 = __ldg(bias + col), b1 = __ldg(bias + col + 1);
#pragma unroll
        for (int mi = 0; mi < 4; mi++) {
            const int r0 = bm + wm*64 + mi*16 + (lid >> 2);
            __nv_bfloat162 p0 = __floats2bfloat162_rn(d[mi][ni][0] + b0, d[mi][ni][1] + b1);
            __nv_bfloat162 p1 = __floats2bfloat162_rn(d[mi][ni][2] + b0, d[mi][ni][3] + b1);
            *(__nv_bfloat162*)(g_cb + (size_t)r0 * C_DIM + col)       = p0;
            *(__nv_bfloat162*)(g_cb + (size_t)(r0 + 8) * C_DIM + col) = p1;
        }
    }
}

// table[c, o] = log_softmax_o(h2o_w[o, c] + h2o_b[o]); shuffle reductions.
__global__ void build_table(const float* __restrict__ w, const float* __restrict__ b)
{
    __shared__ float wred[16];
    __shared__ float wsum[16];
    const int c = blockIdx.x, o = threadIdx.x;
    const int lw = o >> 5, lid = o & 31;
    float v = w[(size_t)o * C_DIM + c] + b[o];

    float m = v;
#pragma unroll
    for (int off = 16; off > 0; off >>= 1)
        m = fmaxf(m, __shfl_xor_sync(0xffffffffu, m, off));
    if (lid == 0) wred[lw] = m;
    __syncthreads();
    float mx = wred[0];
#pragma unroll
    for (int i = 1; i < 16; i++) mx = fmaxf(mx, wred[i]);

    float e = expf(v - mx);
    float s = e;
#pragma unroll
    for (int off = 16; off > 0; off >>= 1)
        s += __shfl_xor_sync(0xffffffffu, s, off);
    if (lid == 0) wsum[lw] = s;
    __syncthreads();
    float tot = 0.0f;
#pragma unroll
    for (int i = 0; i < 16; i++) tot += wsum[i];

    g_table[(size_t)c * O_DIM + o] = v - (logf(tot) + mx);
}

// ---------------------------------------------------------------------------
// Scan + exact refinement + output write. One warp per row.
// ---------------------------------------------------------------------------
__global__ void __launch_bounds__(256)
scan_out(const float* __restrict__ w, const float* __restrict__ b,
         float* __restrict__ out)
{
    __shared__ int cnt[8];
    __shared__ int cand[8][64];
    const int wid = threadIdx.x >> 5, lid = threadIdx.x & 31;
    const int row = blockIdx.x * 8 + wid;

    const uint4* c4 = (const uint4*)(g_cb + (size_t)row * C_DIM);
    float mx = -1e30f;
    uint4 qv[4];
#pragma unroll
    for (int it = 0; it < 4; it++) {
        qv[it] = c4[lid + it * 32];
        const uint32_t* u = (const uint32_t*)&qv[it];
#pragma unroll
        for (int e = 0; e < 4; e++) {
            __nv_bfloat162 p = *(const __nv_bfloat162*)&u[e];
            mx = fmaxf(mx, fmaxf(__bfloat162float(p.x), __bfloat162float(p.y)));
        }
    }
#pragma unroll
    for (int off = 16; off > 0; off >>= 1)
        mx = fmaxf(mx, __shfl_xor_sync(0xffffffffu, mx, off));

    float margin = 0.06f * fabsf(mx) + 1e-5f;
    float thr = mx - margin;
    if (lid == 0) cnt[wid] = 0;
    __syncwarp();
#pragma unroll
    for (int it = 0; it < 4; it++) {
        const uint32_t* u = (const uint32_t*)&qv[it];
#pragma unroll
        for (int e = 0; e < 4; e++) {
            __nv_bfloat162 p = *(const __nv_bfloat162*)&u[e];
            int j0 = (lid + it * 32) * 8 + e * 2;
            if (__bfloat162float(p.x) >= thr) {
                int q = atomicAdd(&cnt[wid], 1);
                if (q < 64) cand[wid][q] = j0;
            }
            if (__bfloat162float(p.y) >= thr) {
                int q = atomicAdd(&cnt[wid], 1);
                if (q < 64) cand[wid][q] = j0 + 1;
            }
        }
    }
    __syncwarp();
    int n = min(cnt[wid], 64);

    const float* hrow = g_h + (size_t)row * H_DIM;
    float best = -1e30f; int bidx = C_DIM;
    for (int ci = 0; ci < n; ci++) {
        int j = cand[wid][ci];
        const float* wr = w + (size_t)j * H_DIM;
        float s = 0.0f;
#pragma unroll
        for (int i = 0; i < 16; i++) {
            int k = lid + i * 32;
            s = fmaf(hrow[k], wr[k], s);
        }
#pragma unroll
        for (int off = 16; off > 0; off >>= 1)
            s += __shfl_xor_sync(0xffffffffu, s, off);
        s += b[j];
        if (s > best || (s == best && j < bidx)) { best = s; bidx = j; }
    }
    bidx = __shfl_sync(0xffffffffu, bidx, 0);
    const float4* src = (const float4*)(g_table + (size_t)bidx * O_DIM);
    float4* dst = (float4*)(out + (size_t)row * O_DIM);
#pragma unroll
    for (int i = 0; i < 4; i++)
        dst[lid + i * 32] = src[lid + i * 32];
}

extern "C" void kernel_launch(void* const* d_in, const int* in_sizes, int n_in,
                              void* d_out, int out_size)
{
    const float* x     = (const float*)d_in[0];
    const float* i2m_w = (const float*)d_in[2];
    const float* i2m_b = (const float*)d_in[3];
    const float* m2h_w = (const float*)d_in[4];
    const float* m2h_b = (const float*)d_in[5];
    const float* h2o_w = (const float*)d_in[6];
    const float* h2o_b = (const float*)d_in[7];
    float* out = (float*)d_out;

    cudaFuncSetAttribute(gemm1_mma, cudaFuncAttributeMaxDynamicSharedMemorySize, SMEM_DYN);
    cudaFuncSetAttribute(gemm2_mma, cudaFuncAttributeMaxDynamicSharedMemorySize, SMEM_DYN);

    // prep: splits + conversions + table (all independent)
    split_x<<<(ROWS*I_DIM/4)/256, 256>>>(x);
    split_w1<<<(H_DIM*I_DIM/4)/256, 256>>>(i2m_w);
    conv_w2<<<(C_DIM*H_DIM/4)/256, 256>>>(m2h_w);
    build_table<<<C_DIM, O_DIM>>>(h2o_w, h2o_b);

    // 1) h = relu(x @ i2m_w^T + b)  (bf16x6 exact on tensor cores)
    gemm1_mma<<<dim3(H_DIM/128, ROWS/128), 256, SMEM_DYN>>>(i2m_b);

    // 2) approx c = h_bf16 @ w_bf16^T + b  -> bf16
    gemm2_mma<<<dim3(C_DIM/128, ROWS/128), 256, SMEM_DYN>>>(m2h_b);

    // 3) winner per row (fp32-verified) + output write
    scan_out<<<ROWS/8, 256>>>(m2h_w, m2h_b, out);
}

// round 7
// speedup vs baseline: 3.1351x; 1.0515x over previous
#include <cuda_runtime.h>
#include <cuda_bf16.h>
#include <stdint.h>

// Problem dims
#define ROWS   32768          // T*B
#define I_DIM  256
#define H_DIM  512
#define C_DIM  1024
#define O_DIM  512

// Scratch (device globals: no allocation allowed)
__device__ float         g_h[(size_t)ROWS * H_DIM];     // fp32 hidden (fp32-grade exact)
__device__ __nv_bfloat16 g_hb[(size_t)ROWS * H_DIM];    // bf16 hidden
__device__ __nv_bfloat16 g_w2b[(size_t)C_DIM * H_DIM];  // bf16 m2h_w
__device__ __nv_bfloat16 g_cb[(size_t)ROWS * C_DIM];    // approx concept pre-acts (bf16)
__device__ float         g_table[(size_t)C_DIM * O_DIM];// log_softmax table

// bf16 splits of x [ROWS, I_DIM] and i2m_w [H_DIM, I_DIM]
__device__ __nv_bfloat16 g_x1[(size_t)ROWS * I_DIM];
__device__ __nv_bfloat16 g_x2[(size_t)ROWS * I_DIM];
__device__ __nv_bfloat16 g_x3[(size_t)ROWS * I_DIM];
__device__ __nv_bfloat16 g_v1[(size_t)H_DIM * I_DIM];
__device__ __nv_bfloat16 g_v2[(size_t)H_DIM * I_DIM];
__device__ __nv_bfloat16 g_v3[(size_t)H_DIM * I_DIM];

// ---------------------------------------------------------------------------
// PTX helpers (base sm_103 ISA: cp.async / ldmatrix / mma.sync)
// ---------------------------------------------------------------------------
__device__ __forceinline__ uint32_t smem_u32(const void* p) {
    uint32_t a;
    asm("{ .reg .u64 t; cvta.to.shared.u64 t, %1; cvt.u32.u64 %0, t; }" : "=r"(a) : "l"(p));
    return a;
}
#define CP_ASYNC16(dst, src) \
    asm volatile("cp.async.cg.shared.global [%0], [%1], 16;" :: "r"(dst), "l"(src) : "memory")
#define CP_COMMIT()  asm volatile("cp.async.commit_group;" ::: "memory")
#define CP_WAIT(n)   asm volatile("cp.async.wait_group %0;" :: "n"(n) : "memory")

__device__ __forceinline__ void ldsm_x4(uint32_t& r0, uint32_t& r1, uint32_t& r2, uint32_t& r3,
                                        uint32_t addr) {
    asm volatile("ldmatrix.sync.aligned.m8n8.x4.shared.b16 {%0,%1,%2,%3}, [%4];"
                 : "=r"(r0), "=r"(r1), "=r"(r2), "=r"(r3) : "r"(addr));
}
__device__ __forceinline__ void mma_bf16(float* d, const uint32_t* a, const uint32_t* b) {
    asm volatile("mma.sync.aligned.m16n8k16.row.col.f32.bf16.bf16.f32 "
                 "{%0,%1,%2,%3}, {%4,%5,%6,%7}, {%8,%9}, {%0,%1,%2,%3};"
                 : "+f"(d[0]), "+f"(d[1]), "+f"(d[2]), "+f"(d[3])
                 : "r"(a[0]), "r"(a[1]), "r"(a[2]), "r"(a[3]), "r"(b[0]), "r"(b[1]));
}

// ---------------------------------------------------------------------------
// split kernels: fp32 -> 3-way bf16 split (x = x1 + x2 + x3, residual 2^-27)
// ---------------------------------------------------------------------------
__device__ __forceinline__ void split3(float v, __nv_bfloat16& a, __nv_bfloat16& b,
                                       __nv_bfloat16& c) {
    a = __float2bfloat16(v);
    float r1 = v - __bfloat162float(a);
    b = __float2bfloat16(r1);
    float r2 = r1 - __bfloat162float(b);
    c = __float2bfloat16(r2);
}

__global__ void split_x(const float* __restrict__ x)
{
    size_t i = (size_t)blockIdx.x * 256 + threadIdx.x;
    float4 v = *(const float4*)(x + i * 4);
    __nv_bfloat16 a[4], b[4], c[4];
    split3(v.x, a[0], b[0], c[0]);
    split3(v.y, a[1], b[1], c[1]);
    split3(v.z, a[2], b[2], c[2]);
    split3(v.w, a[3], b[3], c[3]);
    *(uint2*)(g_x1 + i * 4) = *(uint2*)a;
    *(uint2*)(g_x2 + i * 4) = *(uint2*)b;
    *(uint2*)(g_x3 + i * 4) = *(uint2*)c;
}

__global__ void split_w1(const float* __restrict__ w)
{
    size_t i = (size_t)blockIdx.x * 256 + threadIdx.x;
    float4 v = *(const float4*)(w + i * 4);
    __nv_bfloat16 a[4], b[4], c[4];
    split3(v.x, a[0], b[0], c[0]);
    split3(v.y, a[1], b[1], c[1]);
    split3(v.z, a[2], b[2], c[2]);
    split3(v.w, a[3], b[3], c[3]);
    *(uint2*)(g_v1 + i * 4) = *(uint2*)a;
    *(uint2*)(g_v2 + i * 4) = *(uint2*)b;
    *(uint2*)(g_v3 + i * 4) = *(uint2*)c;
}

// convert m2h_w (fp32 [C,H]) -> bf16
__global__ void conv_w2(const float* __restrict__ w)
{
    size_t i = (size_t)blockIdx.x * 256 + threadIdx.x;
    float4 v = *(const float4*)(w + i * 4);
    __nv_bfloat16 b[4] = { __float2bfloat16(v.x), __float2bfloat16(v.y),
                           __float2bfloat16(v.z), __float2bfloat16(v.w) };
    *(uint2*)(g_w2b + i * 4) = *(uint2*)b;
}

// ---------------------------------------------------------------------------
// Pipelined HMMA GEMM core constants
// 128x128 block, 4 warps (2x2), warp tile 64x64, BK=32, 5-stage cp.async.
// ---------------------------------------------------------------------------
#define BK        32
#define SROW      40                      // padded row length (bf16 elems) = 80B
#define STAGE_HB  (128 * SROW * 2)        // bytes per half-stage (A or B) = 10240
#define STAGE_SZ  (2 * STAGE_HB)          // 20480
#define STAGES    5
#define SMEM_DYN  (STAGES * STAGE_SZ)     // 102400

// ---------------------------------------------------------------------------
// GEMM1 via bf16x6 HMMA (fp32-exact): g_h = relu(x @ i2m_w^T + b), + bf16 copy.
// 6 accumulating K=256 passes over split pairs. NIT = 48.
// ---------------------------------------------------------------------------
__global__ void __launch_bounds__(128, 2)
gemm1_mma(const float* __restrict__ bias)
{
    extern __shared__ __align__(16) unsigned char smem[];

    const int t   = threadIdx.x;
    const int wid = t >> 5, lid = t & 31;
    const int wm  = wid & 1;              // 2 warp rows (64 each)
    const int wn  = wid >> 1;             // 2 warp cols (64 each)
    const int bm  = blockIdx.y * 128, bn = blockIdx.x * 128;

    const __nv_bfloat16* Aps[6] = { g_x1, g_x1, g_x2, g_x1, g_x2, g_x3 };
    const __nv_bfloat16* Bps[6] = { g_v1, g_v2, g_v1, g_v3, g_v2, g_v1 };

    const uint32_t sbase = smem_u32(smem);

    // cp.async pieces: 512 per matrix per stage, 4 per thread per matrix
    const int rl[4] = { t >> 2, (t + 128) >> 2, (t + 256) >> 2, (t + 384) >> 2 };
    const int sg = t & 3;

    float d[4][8][4];
#pragma unroll
    for (int mi = 0; mi < 4; mi++)
#pragma unroll
        for (int ni = 0; ni < 8; ni++)
#pragma unroll
            for (int r = 0; r < 4; r++) d[mi][ni][r] = 0.0f;

    const int NIT = 6 * (I_DIM / BK);     // 48

#pragma unroll
    for (int p = 0; p < STAGES - 1; p++) {
        const int seg = p >> 3;
        const int k0  = (p & 7) * BK;
        const __nv_bfloat16* Ap = Aps[seg];
        const __nv_bfloat16* Bp = Bps[seg];
        const uint32_t dA = sbase + p * STAGE_SZ;
        const uint32_t dB = dA + STAGE_HB;
#pragma unroll
        for (int i = 0; i < 4; i++) {
            CP_ASYNC16(dA + rl[i]*80 + sg*16, Ap + (size_t)(bm + rl[i])*I_DIM + k0 + sg*8);
            CP_ASYNC16(dB + rl[i]*80 + sg*16, Bp + (size_t)(bn + rl[i])*I_DIM + k0 + sg*8);
        }
        CP_COMMIT();
    }

    const int rowA = wm*64 + (lid & 15);
    const int colAofs = (lid < 16) ? 0 : 8;
    const int rowB = wn*64 + ((lid >> 4) & 1)*8 + (lid & 7);
    const int colBofs = ((lid >> 3) & 1)*8;

    int stage = 0;
    for (int kt = 0; kt < NIT; kt++) {
        CP_WAIT(STAGES - 2);
        __syncthreads();

        const uint32_t aB = sbase + stage * STAGE_SZ;
        const uint32_t bB = aB + STAGE_HB;
#pragma unroll
        for (int ks = 0; ks < BK; ks += 16) {
            uint32_t a[4][4];
#pragma unroll
            for (int mi = 0; mi < 4; mi++)
                ldsm_x4(a[mi][0], a[mi][1], a[mi][2], a[mi][3],
                        aB + (uint32_t)(rowA + mi*16) * 80 + (uint32_t)(ks + colAofs) * 2);
            uint32_t b[8][2];
#pragma unroll
            for (int np = 0; np < 4; np++) {
                uint32_t q0, q1, q2, q3;
                ldsm_x4(q0, q1, q2, q3,
                        bB + (uint32_t)(rowB + np*16) * 80 + (uint32_t)(ks + colBofs) * 2);
                b[np*2][0] = q0; b[np*2][1] = q1;
                b[np*2+1][0] = q2; b[np*2+1][1] = q3;
            }
#pragma unroll
            for (int mi = 0; mi < 4; mi++)
#pragma unroll
                for (int ni = 0; ni < 8; ni++)
                    mma_bf16(d[mi][ni], a[mi], b[ni]);
        }

        const int kn = kt + STAGES - 1;
        if (kn < NIT) {
            const int seg = kn >> 3;
            const int k0  = (kn & 7) * BK;
            const __nv_bfloat16* Ap = Aps[seg];
            const __nv_bfloat16* Bp = Bps[seg];
            const int ws = (stage + STAGES - 1) % STAGES;
            const uint32_t dA = sbase + ws * STAGE_SZ;
            const uint32_t dB = dA + STAGE_HB;
#pragma unroll
            for (int i = 0; i < 4; i++) {
                CP_ASYNC16(dA + rl[i]*80 + sg*16, Ap + (size_t)(bm + rl[i])*I_DIM + k0 + sg*8);
                CP_ASYNC16(dB + rl[i]*80 + sg*16, Bp + (size_t)(bn + rl[i])*I_DIM + k0 + sg*8);
            }
        }
        CP_COMMIT();

        stage = (stage + 1 == STAGES) ? 0 : stage + 1;
    }

    // epilogue: + bias, relu -> g_h (fp32) and g_hb (bf16)
    const int cbase = bn + wn*64 + (lid & 3) * 2;
#pragma unroll
    for (int ni = 0; ni < 8; ni++) {
        const int col = cbase + ni*8;
        const float b0 = __ldg(bias + col), b1 = __ldg(bias + col + 1);
#pragma unroll
        for (int mi = 0; mi < 4; mi++) {
            const int r0 = bm + wm*64 + mi*16 + (lid >> 2);
            float v00 = fmaxf(d[mi][ni][0] + b0, 0.0f);
            float v01 = fmaxf(d[mi][ni][1] + b1, 0.0f);
            float v10 = fmaxf(d[mi][ni][2] + b0, 0.0f);
            float v11 = fmaxf(d[mi][ni][3] + b1, 0.0f);
            *(float2*)(g_h + (size_t)r0 * H_DIM + col)       = make_float2(v00, v01);
            *(float2*)(g_h + (size_t)(r0 + 8) * H_DIM + col) = make_float2(v10, v11);
            *(__nv_bfloat162*)(g_hb + (size_t)r0 * H_DIM + col) =
                __floats2bfloat162_rn(v00, v01);
            *(__nv_bfloat162*)(g_hb + (size_t)(r0 + 8) * H_DIM + col) =
                __floats2bfloat162_rn(v10, v11);
        }
    }
}

// ---------------------------------------------------------------------------
// GEMM2 via mma.sync (HMMA bf16, fp32 accum): g_cb = bf16(g_hb @ g_w2b^T + b)
// NIT = 16, 5-stage pipeline, warp tile 64x64.
// ---------------------------------------------------------------------------
__global__ void __launch_bounds__(128, 2)
gemm2_mma(const float* __restrict__ bias)
{
    extern __shared__ __align__(16) unsigned char smem[];

    const int t   = threadIdx.x;
    const int wid = t >> 5, lid = t & 31;
    const int wm  = wid & 1;
    const int wn  = wid >> 1;
    const int bm  = blockIdx.y * 128, bn = blockIdx.x * 128;

    const uint32_t sbase = smem_u32(smem);

    const int rl[4] = { t >> 2, (t + 128) >> 2, (t + 256) >> 2, (t + 384) >> 2 };
    const int sg = t & 3;

    float d[4][8][4];
#pragma unroll
    for (int mi = 0; mi < 4; mi++)
#pragma unroll
        for (int ni = 0; ni < 8; ni++)
#pragma unroll
            for (int r = 0; r < 4; r++) d[mi][ni][r] = 0.0f;

    const int NIT = H_DIM / BK;           // 16

#pragma unroll
    for (int p = 0; p < STAGES - 1; p++) {
        const int k0 = p * BK;
        const uint32_t dA = sbase + p * STAGE_SZ;
        const uint32_t dB = dA + STAGE_HB;
#pragma unroll
        for (int i = 0; i < 4; i++) {
            CP_ASYNC16(dA + rl[i]*80 + sg*16, g_hb  + (size_t)(bm + rl[i])*H_DIM + k0 + sg*8);
            CP_ASYNC16(dB + rl[i]*80 + sg*16, g_w2b + (size_t)(bn + rl[i])*H_DIM + k0 + sg*8);
        }
        CP_COMMIT();
    }

    const int rowA = wm*64 + (lid & 15);
    const int colAofs = (lid < 16) ? 0 : 8;
    const int rowB = wn*64 + ((lid >> 4) & 1)*8 + (lid & 7);
    const int colBofs = ((lid >> 3) & 1)*8;

    int stage = 0;
    for (int kt = 0; kt < NIT; kt++) {
        CP_WAIT(STAGES - 2);
        __syncthreads();

        const uint32_t aB = sbase + stage * STAGE_SZ;
        const uint32_t bB = aB + STAGE_HB;
#pragma unroll
        for (int ks = 0; ks < BK; ks += 16) {
            uint32_t a[4][4];
#pragma unroll
            for (int mi = 0; mi < 4; mi++)
                ldsm_x4(a[mi][0], a[mi][1], a[mi][2], a[mi][3],
                        aB + (uint32_t)(rowA + mi*16) * 80 + (uint32_t)(ks + colAofs) * 2);
            uint32_t b[8][2];
#pragma unroll
            for (int np = 0; np < 4; np++) {
                uint32_t q0, q1, q2, q3;
                ldsm_x4(q0, q1, q2, q3,
                        bB + (uint32_t)(rowB + np*16) * 80 + (uint32_t)(ks + colBofs) * 2);
                b[np*2][0] = q0; b[np*2][1] = q1;
                b[np*2+1][0] = q2; b[np*2+1][1] = q3;
            }
#pragma unroll
            for (int mi = 0; mi < 4; mi++)
#pragma unroll
                for (int ni = 0; ni < 8; ni++)
                    mma_bf16(d[mi][ni], a[mi], b[ni]);
        }

        const int kn = kt + STAGES - 1;
        if (kn < NIT) {
            const int k0 = kn * BK;
            const int ws = (stage + STAGES - 1) % STAGES;
            const uint32_t dA = sbase + ws * STAGE_SZ;
            const uint32_t dB = dA + STAGE_HB;
#pragma unroll
            for (int i = 0; i < 4; i++) {
                CP_ASYNC16(dA + rl[i]*80 + sg*16, g_hb  + (size_t)(bm + rl[i])*H_DIM + k0 + sg*8);
                CP_ASYNC16(dB + rl[i]*80 + sg*16, g_w2b + (size_t)(bn + rl[i])*H_DIM + k0 + sg*8);
            }
        }
        CP_COMMIT();

        stage = (stage + 1 == STAGES) ? 0 : stage + 1;
    }

    const int cbase = bn + wn*64 + (lid & 3) * 2;
#pragma unroll
    for (int ni = 0; ni < 8; ni++) {
        const int col = cbase + ni*8;
        const float b0 = __ldg(bias + col), b1 = __ldg(bias + col + 1);
#pragma unroll
        for (int mi = 0; mi < 4; mi++) {
            const int r0 = bm + wm*64 + mi*16 + (lid >> 2);
            __nv_bfloat162 p0 = __floats2bfloat162_rn(d[mi][ni][0] + b0, d[mi][ni][1] + b1);
            __nv_bfloat162 p1 = __floats2bfloat162_rn(d[mi][ni][2] + b0, d[mi][ni][3] + b1);
            *(__nv_bfloat162*)(g_cb + (size_t)r0 * C_DIM + col)       = p0;
            *(__nv_bfloat162*)(g_cb + (size_t)(r0 + 8) * C_DIM + col) = p1;
        }
    }
}

// table[c, o] = log_softmax_o(h2o_w[o, c] + h2o_b[o]); shuffle reductions.
__global__ void build_table(const float* __restrict__ w, const float* __restrict__ b)
{
    __shared__ float wred[16];
    __shared__ float wsum[16];
    const int c = blockIdx.x, o = threadIdx.x;
    const int lw = o >> 5, lid = o & 31;
    float v = w[(size_t)o * C_DIM + c] + b[o];

    float m = v;
#pragma unroll
    for (int off = 16; off > 0; off >>= 1)
        m = fmaxf(m, __shfl_xor_sync(0xffffffffu, m, off));
    if (lid == 0) wred[lw] = m;
    __syncthreads();
    float mx = wred[0];
#pragma unroll
    for (int i = 1; i < 16; i++) mx = fmaxf(mx, wred[i]);

    float e = expf(v - mx);
    float s = e;
#pragma unroll
    for (int off = 16; off > 0; off >>= 1)
        s += __shfl_xor_sync(0xffffffffu, s, off);
    if (lid == 0) wsum[lw] = s;
    __syncthreads();
    float tot = 0.0f;
#pragma unroll
    for (int i = 0; i < 16; i++) tot += wsum[i];

    g_table[(size_t)c * O_DIM + o] = v - (logf(tot) + mx);
}

// ---------------------------------------------------------------------------
// Scan + exact refinement + output write. One warp per row.
// ---------------------------------------------------------------------------
__global__ void __launch_bounds__(256)
scan_out(const float* __restrict__ w, const float* __restrict__ b,
         float* __restrict__ out)
{
    __shared__ int cnt[8];
    __shared__ int cand[8][64];
    const int wid = threadIdx.x >> 5, lid = threadIdx.x & 31;
    const int row = blockIdx.x * 8 + wid;

    const uint4* c4 = (const uint4*)(g_cb + (size_t)row * C_DIM);
    float mx = -1e30f;
    uint4 qv[4];
#pragma unroll
    for (int it = 0; it < 4; it++) {
        qv[it] = c4[lid + it * 32];
        const uint32_t* u = (const uint32_t*)&qv[it];
#pragma unroll
        for (int e = 0; e < 4; e++) {
            __nv_bfloat162 p = *(const __nv_bfloat162*)&u[e];
            mx = fmaxf(mx, fmaxf(__bfloat162float(p.x), __bfloat162float(p.y)));
        }
    }
#pragma unroll
    for (int off = 16; off > 0; off >>= 1)
        mx = fmaxf(mx, __shfl_xor_sync(0xffffffffu, mx, off));

    float margin = 0.06f * fabsf(mx) + 1e-5f;
    float thr = mx - margin;
    if (lid == 0) cnt[wid] = 0;
    __syncwarp();
#pragma unroll
    for (int it = 0; it < 4; it++) {
        const uint32_t* u = (const uint32_t*)&qv[it];
#pragma unroll
        for (int e = 0; e < 4; e++) {
            __nv_bfloat162 p = *(const __nv_bfloat162*)&u[e];
            int j0 = (lid + it * 32) * 8 + e * 2;
            if (__bfloat162float(p.x) >= thr) {
                int q = atomicAdd(&cnt[wid], 1);
                if (q < 64) cand[wid][q] = j0;
            }
            if (__bfloat162float(p.y) >= thr) {
                int q = atomicAdd(&cnt[wid], 1);
                if (q < 64) cand[wid][q] = j0 + 1;
            }
        }
    }
    __syncwarp();
    int n = min(cnt[wid], 64);

    const float* hrow = g_h + (size_t)row * H_DIM;
    float best = -1e30f; int bidx = C_DIM;
    for (int ci = 0; ci < n; ci++) {
        int j = cand[wid][ci];
        const float* wr = w + (size_t)j * H_DIM;
        float s = 0.0f;
#pragma unroll
        for (int i = 0; i < 16; i++) {
            int k = lid + i * 32;
            s = fmaf(hrow[k], wr[k], s);
        }
#pragma unroll
        for (int off = 16; off > 0; off >>= 1)
            s += __shfl_xor_sync(0xffffffffu, s, off);
        s += b[j];
        if (s > best || (s == best && j < bidx)) { best = s; bidx = j; }
    }
    bidx = __shfl_sync(0xffffffffu, bidx, 0);
    const float4* src = (const float4*)(g_table + (size_t)bidx * O_DIM);
    float4* dst = (float4*)(out + (size_t)row * O_DIM);
#pragma unroll
    for (int i = 0; i < 4; i++)
        dst[lid + i * 32] = src[lid + i * 32];
}

extern "C" void kernel_launch(void* const* d_in, const int* in_sizes, int n_in,
                              void* d_out, int out_size)
{
    const float* x     = (const float*)d_in[0];
    const float* i2m_w = (const float*)d_in[2];
    const float* i2m_b = (const float*)d_in[3];
    const float* m2h_w = (const float*)d_in[4];
    const float* m2h_b = (const float*)d_in[5];
    const float* h2o_w = (const float*)d_in[6];
    const float* h2o_b = (const float*)d_in[7];
    float* out = (float*)d_out;

    cudaFuncSetAttribute(gemm1_mma, cudaFuncAttributeMaxDynamicSharedMemorySize, SMEM_DYN);
    cudaFuncSetAttribute(gemm2_mma, cudaFuncAttributeMaxDynamicSharedMemorySize, SMEM_DYN);

    // prep: splits + conversions + table (all independent)
    split_x<<<(ROWS*I_DIM/4)/256, 256>>>(x);
    split_w1<<<(H_DIM*I_DIM/4)/256, 256>>>(i2m_w);
    conv_w2<<<(C_DIM*H_DIM/4)/256, 256>>>(m2h_w);
    build_table<<<C_DIM, O_DIM>>>(h2o_w, h2o_b);

    // 1) h = relu(x @ i2m_w^T + b)  (bf16x6 exact on tensor cores)
    gemm1_mma<<<dim3(H_DIM/128, ROWS/128), 128, SMEM_DYN>>>(i2m_b);

    // 2) approx c = h_bf16 @ w_bf16^T + b  -> bf16
    gemm2_mma<<<dim3(C_DIM/128, ROWS/128), 128, SMEM_DYN>>>(m2h_b);

    // 3) winner per row (fp32-verified) + output write
    scan_out<<<ROWS/8, 256>>>(m2h_w, m2h_b, out);
}